// round 13
// baseline (speedup 1.0000x reference)
#include <cuda_runtime.h>
#include <cuda_bf16.h>
#include <math.h>
#include <stdint.h>

#define NNODE   50000
#define NEDGE   800000
#define ET      850000      // NEDGE + NNODE self loops
#define ECAND   200000
#define MPAD    50048       // ceil(NNODE/128)*128
#define KMAX    384
#define NBLK    49          // ceil(NNODE/1024)

// ---------------- scratch (device globals; no allocation) ----------------
__device__ __align__(16) __nv_bfloat16 g_pAh[MPAD * KMAX];  // A hi plane
__device__ __align__(16) __nv_bfloat16 g_pAl[MPAD * KMAX];  // A lo plane
// packed W planes [N][K]: L1 @0 (384*256), L2 @98304 (256*64), L3 @114688 (64*128)
__device__ __align__(16) __nv_bfloat16 g_pBh[122880];
__device__ __align__(16) __nv_bfloat16 g_pBl[122880];
__device__ __align__(16) float  g_h[NNODE * 256];           // GEMM output (fp32)
// ping-pong alpha buffers
__device__ float4 g_alpha_sA[NNODE];
__device__ float4 g_alpha_dA[NNODE];
__device__ float4 g_alpha_sB[NNODE];
__device__ float4 g_alpha_dB[NNODE];
__device__ int    g_esrc[ET];
__device__ int    g_rowoff[NNODE + 1];
__device__ int    g_cnt[NNODE];
__device__ int    g_cursor[NNODE];
__device__ int    g_bsum[64];
__device__ int    g_boff[64];
__device__ __align__(16) float g_z[NNODE * 32];
__device__ int    g_idx64_ei;
__device__ int    g_idx64_eli;

// ---------------- helpers ----------------
__device__ __forceinline__ float lrelu(float v) { return v > 0.f ? v : 0.2f * v; }

__device__ __forceinline__ float sel4(float4 v, int h) {
    return h < 2 ? (h == 0 ? v.x : v.y) : (h == 2 ? v.z : v.w);
}

__device__ __forceinline__ int load_idx(const void* p, int use64, long long pos) {
    return use64 ? (int)((const long long*)p)[pos] : ((const int*)p)[pos];
}

__device__ __forceinline__ void cvt_split(float v, __nv_bfloat16& h, __nv_bfloat16& l) {
    h = __float2bfloat16(v);
    l = __float2bfloat16(v - __bfloat162float(h));
}

__device__ __forceinline__ void cp16(const void* s, const void* g) {
    uint32_t sa = (uint32_t)__cvta_generic_to_shared(s);
    asm volatile("cp.async.cg.shared.global [%0], [%1], 16;\n" :: "r"(sa), "l"(g));
}

// per-edge: ex for one head, computed warp-wide (lane L evals head L&3),
// fetched per-lane via shfl. No max subtraction (softmax is shift-invariant;
// |e| <~ 15 here so exp stays far from fp32 limits).
__device__ __forceinline__ float edge_ex(const float4* __restrict__ a_s,
                                         int e, float4 ad, int myh,
                                         int want, int& src) {
    src = g_esrc[e];
    float4 s = a_s[src];
    float eh = sel4(make_float4(lrelu(s.x + ad.x), lrelu(s.y + ad.y),
                                lrelu(s.z + ad.z), lrelu(s.w + ad.w)), myh);
    float ex = __expf(eh);
    return __shfl_sync(0xffffffffu, ex, want);
}

// ---------------- init: dtype detect + cnt=1 + alphaA zero ----------------
__global__ void init_detect(const int* __restrict__ ei, const int* __restrict__ eli) {
    int i = blockIdx.x * blockDim.x + threadIdx.x;
    if (i < NNODE) {
        g_cnt[i] = 1;
        g_alpha_sA[i] = make_float4(0, 0, 0, 0);
        g_alpha_dA[i] = make_float4(0, 0, 0, 0);
    }
    if (i == 0) {
        int ok = 1;
        #pragma unroll
        for (int j = 1; j < 64; j += 2) if (ei[j] != 0) { ok = 0; break; }
        g_idx64_ei = ok;
        ok = 1;
        #pragma unroll
        for (int j = 1; j < 64; j += 2) if (eli[j] != 0) { ok = 0; break; }
        g_idx64_eli = ok;
    }
}

// ================= operand splitting (x + all weights, one launch) =========
#define NX4 (NNODE * 384 / 4)
__global__ void split_all(const float* __restrict__ x, const float* __restrict__ W1,
                          const float* __restrict__ W2, const float* __restrict__ W3) {
    int t = blockIdx.x * blockDim.x + threadIdx.x;
    if (t < NX4) {
        long i = (long)t * 4;
        float4 v = *(const float4*)(x + i);
        __nv_bfloat16 h0, h1, h2, h3, l0, l1, l2, l3;
        cvt_split(v.x, h0, l0); cvt_split(v.y, h1, l1);
        cvt_split(v.z, h2, l2); cvt_split(v.w, h3, l3);
        *(__nv_bfloat162*)&g_pAh[i]     = __nv_bfloat162(h0, h1);
        *(__nv_bfloat162*)&g_pAh[i + 2] = __nv_bfloat162(h2, h3);
        *(__nv_bfloat162*)&g_pAl[i]     = __nv_bfloat162(l0, l1);
        *(__nv_bfloat162*)&g_pAl[i + 2] = __nv_bfloat162(l2, l3);
        return;
    }
    int i = t - NX4;
    const float* W; int K, N, off, li;
    if (i < 98304)       { W = W1; K = 384; N = 256; off = 0;      li = i; }
    else if (i < 114688) { W = W2; K = 256; N = 64;  off = 98304;  li = i - 98304; }
    else if (i < 122880) { W = W3; K = 64;  N = 128; off = 114688; li = i - 114688; }
    else return;
    int k = li / N, n = li % N;
    __nv_bfloat16 h, l;
    cvt_split(W[li], h, l);
    g_pBh[off + n * K + k] = h;
    g_pBl[off + n * K + k] = l;
}

// ================= CSR build (parallel scan) =================
__global__ void hist_edges(const void* __restrict__ ei) {
    int e = blockIdx.x * blockDim.x + threadIdx.x;
    if (e >= NEDGE) return;
    int dst = load_idx(ei, g_idx64_ei, (long long)NEDGE + e);
    atomicAdd(&g_cnt[dst], 1);
}

__global__ void csr_s1() {
    __shared__ int ws[32];
    int i = blockIdx.x * 1024 + threadIdx.x;
    int lane = threadIdx.x & 31, wid = threadIdx.x >> 5;
    int v = (i < NNODE) ? g_cnt[i] : 0;
    #pragma unroll
    for (int o = 16; o; o >>= 1) v += __shfl_xor_sync(0xffffffffu, v, o);
    if (lane == 0) ws[wid] = v;
    __syncthreads();
    if (threadIdx.x < 32) {
        int s = ws[threadIdx.x];
        #pragma unroll
        for (int o = 16; o; o >>= 1) s += __shfl_xor_sync(0xffffffffu, s, o);
        if (threadIdx.x == 0) g_bsum[blockIdx.x] = s;
    }
}

__global__ void csr_s2() {
    __shared__ int w0tot;
    int t = threadIdx.x;
    int lane = t & 31, w = t >> 5;
    int v = (t < NBLK) ? g_bsum[t] : 0;
    int x = v;
    #pragma unroll
    for (int o = 1; o < 32; o <<= 1) {
        int y = __shfl_up_sync(0xffffffffu, x, o);
        if (lane >= o) x += y;
    }
    if (t == 31) w0tot = x;
    __syncthreads();
    if (w == 1) x += w0tot;
    if (t < NBLK) g_boff[t] = x - v;
}

__global__ void csr_s3() {
    __shared__ int ws[32];
    int i = blockIdx.x * 1024 + threadIdx.x;
    int lane = threadIdx.x & 31, wid = threadIdx.x >> 5;
    int v = (i < NNODE) ? g_cnt[i] : 0;
    int x = v;
    #pragma unroll
    for (int o = 1; o < 32; o <<= 1) {
        int y = __shfl_up_sync(0xffffffffu, x, o);
        if (lane >= o) x += y;
    }
    if (lane == 31) ws[wid] = x;
    __syncthreads();
    if (wid == 0) {
        int s = ws[lane];
        #pragma unroll
        for (int o = 1; o < 32; o <<= 1) {
            int y = __shfl_up_sync(0xffffffffu, s, o);
            if (lane >= o) s += y;
        }
        ws[lane] = s;
    }
    __syncthreads();
    int ex = x - v + (wid ? ws[wid - 1] : 0) + g_boff[blockIdx.x];
    if (i < NNODE) {
        g_rowoff[i] = ex;
        g_cursor[i] = ex + 1;
        g_esrc[ex] = i;
        if (i == NNODE - 1) g_rowoff[NNODE] = ex + v;
    }
}

__global__ void scatter_edges(const void* __restrict__ ei) {
    int e = blockIdx.x * blockDim.x + threadIdx.x;
    if (e >= NEDGE) return;
    int use64 = g_idx64_ei;
    int src = load_idx(ei, use64, e);
    int dst = load_idx(ei, use64, (long long)NEDGE + e);
    int pos = atomicAdd(&g_cursor[dst], 1);
    g_esrc[pos] = src;
}

// ======= split-bf16 mma.sync GEMM, 3-stage cp.async + fused alpha =========
#define BKP 40
#define A_SZ (128 * BKP)
#define B_SZ (64 * BKP)
#define STG  (2 * A_SZ + 2 * B_SZ)
#define NSTAGE 3
#define GEMM_SMEM (NSTAGE * STG * 2)   // 92160 bytes

__device__ __forceinline__ void mma16816(float* c, const uint32_t* a, const uint32_t* b) {
    asm volatile(
        "mma.sync.aligned.m16n8k16.row.col.f32.bf16.bf16.f32 "
        "{%0,%1,%2,%3}, {%4,%5,%6,%7}, {%8,%9}, {%0,%1,%2,%3};\n"
        : "+f"(c[0]), "+f"(c[1]), "+f"(c[2]), "+f"(c[3])
        : "r"(a[0]), "r"(a[1]), "r"(a[2]), "r"(a[3]), "r"(b[0]), "r"(b[1]));
}

__global__ __launch_bounds__(256) void gemm_tc(const __nv_bfloat16* __restrict__ Ah,
                                               const __nv_bfloat16* __restrict__ Al,
                                               const __nv_bfloat16* __restrict__ Bth,
                                               const __nv_bfloat16* __restrict__ Btl,
                                               float* __restrict__ C,
                                               const float* __restrict__ a_s,
                                               const float* __restrict__ a_d,
                                               float* __restrict__ alpha_s_out,
                                               float* __restrict__ alpha_d_out,
                                               int M, int N, int K, int Ch) {
    extern __shared__ __nv_bfloat16 sm[];
    const int tid  = threadIdx.x;
    const int lane = tid & 31;
    const int warp = tid >> 5;
    const int wm   = warp & 3;
    const int wn   = warp >> 2;
    const int tr   = lane >> 2;
    const int tc   = lane & 3;
    const int row0 = blockIdx.y * 128;
    const int col0 = blockIdx.x * 64;
    const int KT   = K / 32;

    float acc[2][4][4] = {};

    auto stage_load = [&](int s, int kt) {
        if (kt < KT) {
            int k0 = kt * 32;
            __nv_bfloat16* sAh = sm + s * STG;
            __nv_bfloat16* sAl = sAh + A_SZ;
            __nv_bfloat16* sBh = sAl + A_SZ;
            __nv_bfloat16* sBl = sBh + B_SZ;
            #pragma unroll
            for (int i = 0; i < 2; i++) {
                int id = tid + i * 256;
                int row = id >> 2, c = id & 3;
                long gofs = (long)(row0 + row) * K + k0 + c * 8;
                cp16(sAh + row * BKP + c * 8, Ah + gofs);
                cp16(sAl + row * BKP + c * 8, Al + gofs);
            }
            {
                int n = tid >> 2, c = tid & 3;
                long gofs = (long)(col0 + n) * K + k0 + c * 8;
                cp16(sBh + n * BKP + c * 8, Bth + gofs);
                cp16(sBl + n * BKP + c * 8, Btl + gofs);
            }
        }
        asm volatile("cp.async.commit_group;\n" ::: "memory");
    };

    auto compute = [&](int s) {
        const __nv_bfloat16* sAh = sm + s * STG;
        const __nv_bfloat16* sAl = sAh + A_SZ;
        const __nv_bfloat16* sBh = sAl + A_SZ;
        const __nv_bfloat16* sBl = sBh + B_SZ;
        #pragma unroll
        for (int ks = 0; ks < 32; ks += 16) {
            uint32_t ah[2][4], al[2][4], bh[4][2], bl[4][2];
            #pragma unroll
            for (int f = 0; f < 2; f++) {
                int r = wm * 32 + f * 16 + tr;
                int kk = ks + tc * 2;
                ah[f][0] = *(const uint32_t*)&sAh[r * BKP + kk];
                ah[f][1] = *(const uint32_t*)&sAh[(r + 8) * BKP + kk];
                ah[f][2] = *(const uint32_t*)&sAh[r * BKP + kk + 8];
                ah[f][3] = *(const uint32_t*)&sAh[(r + 8) * BKP + kk + 8];
                al[f][0] = *(const uint32_t*)&sAl[r * BKP + kk];
                al[f][1] = *(const uint32_t*)&sAl[(r + 8) * BKP + kk];
                al[f][2] = *(const uint32_t*)&sAl[r * BKP + kk + 8];
                al[f][3] = *(const uint32_t*)&sAl[(r + 8) * BKP + kk + 8];
            }
            #pragma unroll
            for (int g = 0; g < 4; g++) {
                int n = wn * 32 + g * 8 + tr;
                int kk = ks + tc * 2;
                bh[g][0] = *(const uint32_t*)&sBh[n * BKP + kk];
                bh[g][1] = *(const uint32_t*)&sBh[n * BKP + kk + 8];
                bl[g][0] = *(const uint32_t*)&sBl[n * BKP + kk];
                bl[g][1] = *(const uint32_t*)&sBl[n * BKP + kk + 8];
            }
            #pragma unroll
            for (int f = 0; f < 2; f++)
                #pragma unroll
                for (int g = 0; g < 4; g++) {
                    mma16816(acc[f][g], ah[f], bh[g]);
                    mma16816(acc[f][g], ah[f], bl[g]);
                    mma16816(acc[f][g], al[f], bh[g]);
                }
        }
    };

    stage_load(0, 0);
    stage_load(1, 1);
    for (int kt = 0; kt < KT; kt++) {
        asm volatile("cp.async.wait_group 1;\n" ::: "memory");
        __syncthreads();
        stage_load((kt + 2) % NSTAGE, kt + 2);
        compute(kt % NSTAGE);
    }

    // ---- store C ----
    #pragma unroll
    for (int f = 0; f < 2; f++) {
        int r = row0 + wm * 32 + f * 16 + tr;
        #pragma unroll
        for (int g = 0; g < 4; g++) {
            int c = col0 + wn * 32 + g * 8 + tc * 2;
            if (r < M)
                *(float2*)&C[(long)r * N + c] = make_float2(acc[f][g][0], acc[f][g][1]);
            if (r + 8 < M)
                *(float2*)&C[(long)(r + 8) * N + c] = make_float2(acc[f][g][2], acc[f][g][3]);
        }
    }

    // ---- fused alpha epilogue ----
    float asv[8], adv[8];
    #pragma unroll
    for (int g = 0; g < 4; g++) {
        int colg = col0 + wn * 32 + g * 8 + tc * 2;
        asv[g * 2] = __ldg(&a_s[colg]); asv[g * 2 + 1] = __ldg(&a_s[colg + 1]);
        adv[g * 2] = __ldg(&a_d[colg]); adv[g * 2 + 1] = __ldg(&a_d[colg + 1]);
    }
    const int hlo = (col0 + wn * 32) / Ch;
    const bool two_heads = (Ch == 16);
    #pragma unroll
    for (int f = 0; f < 2; f++) {
        #pragma unroll
        for (int half = 0; half < 2; half++) {
            int row = row0 + wm * 32 + f * 16 + tr + half * 8;
            float psg[4], pdg[4];
            #pragma unroll
            for (int g = 0; g < 4; g++) {
                float a0 = acc[f][g][half * 2], a1 = acc[f][g][half * 2 + 1];
                psg[g] = a0 * asv[g * 2] + a1 * asv[g * 2 + 1];
                pdg[g] = a0 * adv[g * 2] + a1 * adv[g * 2 + 1];
            }
            float s0 = psg[0] + psg[1], s1 = psg[2] + psg[3];
            float d0 = pdg[0] + pdg[1], d1 = pdg[2] + pdg[3];
            #pragma unroll
            for (int o = 1; o <= 2; o <<= 1) {
                s0 += __shfl_xor_sync(0xffffffffu, s0, o);
                s1 += __shfl_xor_sync(0xffffffffu, s1, o);
                d0 += __shfl_xor_sync(0xffffffffu, d0, o);
                d1 += __shfl_xor_sync(0xffffffffu, d1, o);
            }
            if (tc == 0 && row < M) {
                if (two_heads) {
                    atomicAdd(&alpha_s_out[row * 4 + hlo], s0);
                    atomicAdd(&alpha_s_out[row * 4 + hlo + 1], s1);
                    atomicAdd(&alpha_d_out[row * 4 + hlo], d0);
                    atomicAdd(&alpha_d_out[row * 4 + hlo + 1], d1);
                } else {
                    atomicAdd(&alpha_s_out[row * 4 + hlo], s0 + s1);
                    atomicAdd(&alpha_d_out[row * 4 + hlo], d0 + d1);
                }
            }
        }
    }
}

// ========== fused softmax+aggregate kernels (single pass, no max) ==========

// Layer 1: F=256, C=64. TWO warps per dst node, each owns a 128-feat half
// (1 float4/lane/edge, single head per warp). Unroll-4 edge loop.
__global__ void gat_agg_l1(const float* __restrict__ bias) {
    int gw = (blockIdx.x * blockDim.x + threadIdx.x) >> 5;
    int dstN = gw >> 1;
    int half = gw & 1;
    int lane = threadIdx.x & 31;
    if (dstN >= NNODE) return;
    int r0 = g_rowoff[dstN], r1 = g_rowoff[dstN + 1];
    const float4* a_s = g_alpha_sA;
    float4 ad = g_alpha_dA[dstN];

    const int myh = lane & 3;
    const int hd = half * 2 + (lane >> 4);   // head of feats half*128 + lane*4
    const int voff = half * 32 + lane;       // float4 index within the 256-f row
    float4 acc = make_float4(0, 0, 0, 0);
    float den = 0.f;

    int e = r0;
    for (; e + 3 < r1; e += 4) {
        int s0, s1, s2, s3;
        float x0 = edge_ex(a_s, e,     ad, myh, hd, s0);
        float x1 = edge_ex(a_s, e + 1, ad, myh, hd, s1);
        float x2 = edge_ex(a_s, e + 2, ad, myh, hd, s2);
        float x3 = edge_ex(a_s, e + 3, ad, myh, hd, s3);
        float4 v0 = ((const float4*)(g_h + (long)s0 * 256))[voff];
        float4 v1 = ((const float4*)(g_h + (long)s1 * 256))[voff];
        float4 v2 = ((const float4*)(g_h + (long)s2 * 256))[voff];
        float4 v3 = ((const float4*)(g_h + (long)s3 * 256))[voff];
        acc.x += v0.x * x0 + v1.x * x1 + v2.x * x2 + v3.x * x3;
        acc.y += v0.y * x0 + v1.y * x1 + v2.y * x2 + v3.y * x3;
        acc.z += v0.z * x0 + v1.z * x1 + v2.z * x2 + v3.z * x3;
        acc.w += v0.w * x0 + v1.w * x1 + v2.w * x2 + v3.w * x3;
        den += x0 + x1 + x2 + x3;
    }
    for (; e < r1; e++) {
        int s;
        float x = edge_ex(a_s, e, ad, myh, hd, s);
        float4 v = ((const float4*)(g_h + (long)s * 256))[voff];
        acc.x += v.x * x; acc.y += v.y * x; acc.z += v.z * x; acc.w += v.w * x;
        den += x;
    }

    float iv = 1.f / (den + 1e-16f);
    int f = half * 128 + lane * 4;
    acc.x = acc.x * iv + bias[f];     acc.y = acc.y * iv + bias[f + 1];
    acc.z = acc.z * iv + bias[f + 2]; acc.w = acc.w * iv + bias[f + 3];
    acc.x = acc.x > 0.f ? acc.x : expm1f(acc.x);
    acc.y = acc.y > 0.f ? acc.y : expm1f(acc.y);
    acc.z = acc.z > 0.f ? acc.z : expm1f(acc.z);
    acc.w = acc.w > 0.f ? acc.w : expm1f(acc.w);
    __nv_bfloat16 h0, h1, h2, h3, l0, l1, l2, l3;
    cvt_split(acc.x, h0, l0); cvt_split(acc.y, h1, l1);
    cvt_split(acc.z, h2, l2); cvt_split(acc.w, h3, l3);
    long o = (long)dstN * 256 + f;
    *(__nv_bfloat162*)&g_pAh[o]     = __nv_bfloat162(h0, h1);
    *(__nv_bfloat162*)&g_pAh[o + 2] = __nv_bfloat162(h2, h3);
    *(__nv_bfloat162*)&g_pAl[o]     = __nv_bfloat162(l0, l1);
    *(__nv_bfloat162*)&g_pAl[o + 2] = __nv_bfloat162(l2, l3);
    if (half == 0 && lane == 0) {
        g_alpha_sB[dstN] = make_float4(0, 0, 0, 0);
        g_alpha_dB[dstN] = make_float4(0, 0, 0, 0);
    }
}

// Layer 2: F=64, C=16 -> elu(out+bias) -> split bf16 planes. Unroll-4.
__global__ void gat_agg_l2(const float* __restrict__ bias) {
    int dstN = (blockIdx.x * blockDim.x + threadIdx.x) >> 5;
    int lane = threadIdx.x & 31;
    if (dstN >= NNODE) return;
    int r0 = g_rowoff[dstN], r1 = g_rowoff[dstN + 1];
    const float4* a_s = g_alpha_sB;
    float4 ad = g_alpha_dB[dstN];

    const int myh = lane & 3;
    const int f = lane * 2;
    const int hd = lane >> 3;
    float a0 = 0.f, a1 = 0.f, den = 0.f;

    int e = r0;
    for (; e + 3 < r1; e += 4) {
        int s0, s1, s2, s3;
        float x0 = edge_ex(a_s, e,     ad, myh, hd, s0);
        float x1 = edge_ex(a_s, e + 1, ad, myh, hd, s1);
        float x2 = edge_ex(a_s, e + 2, ad, myh, hd, s2);
        float x3 = edge_ex(a_s, e + 3, ad, myh, hd, s3);
        float2 v0 = *(const float2*)(g_h + (long)s0 * 64 + f);
        float2 v1 = *(const float2*)(g_h + (long)s1 * 64 + f);
        float2 v2 = *(const float2*)(g_h + (long)s2 * 64 + f);
        float2 v3 = *(const float2*)(g_h + (long)s3 * 64 + f);
        a0 += v0.x * x0 + v1.x * x1 + v2.x * x2 + v3.x * x3;
        a1 += v0.y * x0 + v1.y * x1 + v2.y * x2 + v3.y * x3;
        den += x0 + x1 + x2 + x3;
    }
    for (; e < r1; e++) {
        int s;
        float x = edge_ex(a_s, e, ad, myh, hd, s);
        float2 hv = *(const float2*)(g_h + (long)s * 64 + f);
        a0 += hv.x * x; a1 += hv.y * x; den += x;
    }

    float iv = 1.f / (den + 1e-16f);
    a0 = a0 * iv + bias[f];
    a1 = a1 * iv + bias[f + 1];
    a0 = a0 > 0.f ? a0 : expm1f(a0);
    a1 = a1 > 0.f ? a1 : expm1f(a1);
    __nv_bfloat16 h0, h1, l0, l1;
    cvt_split(a0, h0, l0); cvt_split(a1, h1, l1);
    *(__nv_bfloat162*)&g_pAh[(long)dstN * 64 + f] = __nv_bfloat162(h0, h1);
    *(__nv_bfloat162*)&g_pAl[(long)dstN * 64 + f] = __nv_bfloat162(l0, l1);
    if (lane == 0) {
        g_alpha_sA[dstN] = make_float4(0, 0, 0, 0);
        g_alpha_dA[dstN] = make_float4(0, 0, 0, 0);
    }
}

// Layer 3: F=128, C=32, fused head-mean + b3 -> g_z. Unroll-4.
__global__ void gat_agg_l3(const float* __restrict__ b3) {
    int dstN = (blockIdx.x * blockDim.x + threadIdx.x) >> 5;
    int lane = threadIdx.x & 31;
    if (dstN >= NNODE) return;
    int r0 = g_rowoff[dstN], r1 = g_rowoff[dstN + 1];
    const float4* a_s = g_alpha_sA;
    float4 ad = g_alpha_dA[dstN];

    const int myh = lane & 3;
    const int hd = lane >> 3;
    float4 acc = make_float4(0, 0, 0, 0);
    float den = 0.f;

    int e = r0;
    for (; e + 3 < r1; e += 4) {
        int s0, s1, s2, s3;
        float x0 = edge_ex(a_s, e,     ad, myh, hd, s0);
        float x1 = edge_ex(a_s, e + 1, ad, myh, hd, s1);
        float x2 = edge_ex(a_s, e + 2, ad, myh, hd, s2);
        float x3 = edge_ex(a_s, e + 3, ad, myh, hd, s3);
        float4 v0 = ((const float4*)(g_h + (long)s0 * 128))[lane];
        float4 v1 = ((const float4*)(g_h + (long)s1 * 128))[lane];
        float4 v2 = ((const float4*)(g_h + (long)s2 * 128))[lane];
        float4 v3 = ((const float4*)(g_h + (long)s3 * 128))[lane];
        acc.x += v0.x * x0 + v1.x * x1 + v2.x * x2 + v3.x * x3;
        acc.y += v0.y * x0 + v1.y * x1 + v2.y * x2 + v3.y * x3;
        acc.z += v0.z * x0 + v1.z * x1 + v2.z * x2 + v3.z * x3;
        acc.w += v0.w * x0 + v1.w * x1 + v2.w * x2 + v3.w * x3;
        den += x0 + x1 + x2 + x3;
    }
    for (; e < r1; e++) {
        int s;
        float x = edge_ex(a_s, e, ad, myh, hd, s);
        float4 v = ((const float4*)(g_h + (long)s * 128))[lane];
        acc.x += v.x * x; acc.y += v.y * x; acc.z += v.z * x; acc.w += v.w * x;
        den += x;
    }

    float iv = 1.f / (den + 1e-16f);
    acc.x *= iv; acc.y *= iv; acc.z *= iv; acc.w *= iv;
    #pragma unroll
    for (int o = 8; o <= 16; o <<= 1) {
        acc.x += __shfl_xor_sync(0xffffffffu, acc.x, o);
        acc.y += __shfl_xor_sync(0xffffffffu, acc.y, o);
        acc.z += __shfl_xor_sync(0xffffffffu, acc.z, o);
        acc.w += __shfl_xor_sync(0xffffffffu, acc.w, o);
    }
    if (lane < 8) {
        int c = lane * 4;
        float4 z = make_float4(0.25f * acc.x + b3[c],     0.25f * acc.y + b3[c + 1],
                               0.25f * acc.z + b3[c + 2], 0.25f * acc.w + b3[c + 3]);
        *(float4*)&g_z[(long)dstN * 32 + c] = z;
    }
}

// ---------------- logits: dot over 32 dims, warp per candidate edge ----------------
__global__ void dot_kernel(const void* __restrict__ eli, float* __restrict__ out) {
    int w = (blockIdx.x * blockDim.x + threadIdx.x) >> 5;
    int lane = threadIdx.x & 31;
    if (w >= ECAND) return;
    int use64 = g_idx64_eli;
    int s = load_idx(eli, use64, w);
    int d = load_idx(eli, use64, (long long)ECAND + w);
    float p = g_z[(long)s * 32 + lane] * g_z[(long)d * 32 + lane];
    #pragma unroll
    for (int o = 16; o; o >>= 1) p += __shfl_xor_sync(0xffffffffu, p, o);
    if (lane == 0) out[w] = p;
}

// ---------------- host launch ----------------
extern "C" void kernel_launch(void* const* d_in, const int* in_sizes, int n_in,
                              void* d_out, int out_size) {
    const float* x   = (const float*)d_in[0];
    const void*  ei  = d_in[1];
    const void*  eli = d_in[2];
    const float* W1  = (const float*)d_in[3];
    const float* a1s = (const float*)d_in[4];
    const float* a1d = (const float*)d_in[5];
    const float* b1  = (const float*)d_in[6];
    const float* W2  = (const float*)d_in[7];
    const float* a2s = (const float*)d_in[8];
    const float* a2d = (const float*)d_in[9];
    const float* b2  = (const float*)d_in[10];
    const float* W3  = (const float*)d_in[11];
    const float* a3s = (const float*)d_in[12];
    const float* a3d = (const float*)d_in[13];
    const float* b3  = (const float*)d_in[14];
    float* out = (float*)d_out;

    float* p_h;
    cudaGetSymbolAddress((void**)&p_h, g_h);
    __nv_bfloat16 *p_Ah, *p_Al, *p_Bh, *p_Bl;
    cudaGetSymbolAddress((void**)&p_Ah, g_pAh);
    cudaGetSymbolAddress((void**)&p_Al, g_pAl);
    cudaGetSymbolAddress((void**)&p_Bh, g_pBh);
    cudaGetSymbolAddress((void**)&p_Bl, g_pBl);
    float *p_asA, *p_adA, *p_asB, *p_adB;
    cudaGetSymbolAddress((void**)&p_asA, g_alpha_sA);
    cudaGetSymbolAddress((void**)&p_adA, g_alpha_dA);
    cudaGetSymbolAddress((void**)&p_asB, g_alpha_sB);
    cudaGetSymbolAddress((void**)&p_adB, g_alpha_dB);

    static cudaStream_t sB = nullptr;
    static cudaEvent_t evFork = nullptr, evJoin = nullptr;
    static bool attr_done = false;
    if (!attr_done) {
        cudaFuncSetAttribute(gemm_tc, cudaFuncAttributeMaxDynamicSharedMemorySize, GEMM_SMEM);
        cudaStreamCreateWithFlags(&sB, cudaStreamNonBlocking);
        cudaEventCreateWithFlags(&evFork, cudaEventDisableTiming);
        cudaEventCreateWithFlags(&evJoin, cudaEventDisableTiming);
        attr_done = true;
    }

    const int TB = 256;
    const int nodeWarpBlocks  = (NNODE * 32 + TB - 1) / TB;      // 1 warp/node
    const int nodeWarpBlocks2 = (NNODE * 64 + TB - 1) / TB;      // 2 warps/node
    const int MB = (NNODE + 127) / 128;

    // ---- init on main stream ----
    init_detect<<<(NNODE + TB - 1) / TB, TB>>>((const int*)ei, (const int*)eli);
    cudaEventRecord(evFork, 0);

    // ---- fork: CSR build on side stream ----
    cudaStreamWaitEvent(sB, evFork, 0);
    hist_edges<<<(NEDGE + TB - 1) / TB, TB, 0, sB>>>(ei);
    csr_s1<<<NBLK, 1024, 0, sB>>>();
    csr_s2<<<1, 64, 0, sB>>>();
    csr_s3<<<NBLK, 1024, 0, sB>>>();
    scatter_edges<<<(NEDGE + TB - 1) / TB, TB, 0, sB>>>(ei);
    cudaEventRecord(evJoin, sB);

    // ---- main stream: split + layer-1 GEMM concurrently with CSR ----
    split_all<<<(NX4 + 122880 + TB - 1) / TB, TB>>>(x, W1, W2, W3);
    gemm_tc<<<dim3(4, MB), 256, GEMM_SMEM>>>(p_Ah, p_Al, p_Bh, p_Bl, p_h,
                                             a1s, a1d, p_asA, p_adA, NNODE, 256, 384, 64);

    // ---- join: aggregates need the CSR ----
    cudaStreamWaitEvent(0, evJoin, 0);
    gat_agg_l1<<<nodeWarpBlocks2, TB>>>(b1);

    // ---- Layer 2 ----
    gemm_tc<<<dim3(1, MB), 256, GEMM_SMEM>>>(p_Ah, p_Al, p_Bh + 98304, p_Bl + 98304, p_h,
                                             a2s, a2d, p_asB, p_adB, NNODE, 64, 256, 16);
    gat_agg_l2<<<nodeWarpBlocks, TB>>>(b2);

    // ---- Layer 3 ----
    gemm_tc<<<dim3(2, MB), 256, GEMM_SMEM>>>(p_Ah, p_Al, p_Bh + 114688, p_Bl + 114688, p_h,
                                             a3s, a3d, p_asA, p_adA, NNODE, 128, 64, 32);
    gat_agg_l3<<<nodeWarpBlocks, TB>>>(b3);

    // ---- Candidate-edge logits ----
    dot_kernel<<<(ECAND * 32 + TB - 1) / TB, TB>>>(eli, out);
}

// round 15
// speedup vs baseline: 1.0394x; 1.0394x over previous
#include <cuda_runtime.h>
#include <cuda_bf16.h>
#include <math.h>
#include <stdint.h>

#define NNODE   50000
#define NEDGE   800000
#define ET      850000      // NEDGE + NNODE self loops
#define ECAND   200000
#define MPAD    50048       // ceil(NNODE/128)*128
#define KMAX    384
#define NBLK    49          // ceil(NNODE/1024)

// ---------------- scratch (device globals; no allocation) ----------------
__device__ __align__(16) __nv_bfloat16 g_pAh[MPAD * KMAX];  // A hi plane
__device__ __align__(16) __nv_bfloat16 g_pAl[MPAD * KMAX];  // A lo plane
// packed W planes [N][K]: L1 @0 (384*256), L2 @98304 (256*64), L3 @114688 (64*128)
__device__ __align__(16) __nv_bfloat16 g_pBh[122880];
__device__ __align__(16) __nv_bfloat16 g_pBl[122880];
__device__ __align__(16) float  g_h[NNODE * 256];           // GEMM output (fp32)
// ping-pong alpha buffers
__device__ float4 g_alpha_sA[NNODE];
__device__ float4 g_alpha_dA[NNODE];
__device__ float4 g_alpha_sB[NNODE];
__device__ float4 g_alpha_dB[NNODE];
__device__ int    g_esrc[ET];
__device__ int    g_rowoff[NNODE + 1];
__device__ int    g_cnt[NNODE];
__device__ int    g_cursor[NNODE];
__device__ int    g_bsum[64];
__device__ int    g_boff[64];
__device__ __align__(16) float g_z[NNODE * 32];
__device__ int    g_idx64_ei;
__device__ int    g_idx64_eli;

// ---------------- helpers ----------------
__device__ __forceinline__ float lrelu(float v) { return v > 0.f ? v : 0.2f * v; }

__device__ __forceinline__ float sel4(float4 v, int h) {
    return h < 2 ? (h == 0 ? v.x : v.y) : (h == 2 ? v.z : v.w);
}

__device__ __forceinline__ int load_idx(const void* p, int use64, long long pos) {
    return use64 ? (int)((const long long*)p)[pos] : ((const int*)p)[pos];
}

__device__ __forceinline__ void cvt_split(float v, __nv_bfloat16& h, __nv_bfloat16& l) {
    h = __float2bfloat16(v);
    l = __float2bfloat16(v - __bfloat162float(h));
}

__device__ __forceinline__ void cp16(const void* s, const void* g) {
    uint32_t sa = (uint32_t)__cvta_generic_to_shared(s);
    asm volatile("cp.async.cg.shared.global [%0], [%1], 16;\n" :: "r"(sa), "l"(g));
}

// per-edge: ex for one head, computed warp-wide (lane L evals head L&3),
// fetched per-lane via shfl. No max subtraction (softmax is shift-invariant;
// |e| <~ 15 here so exp stays far from fp32 limits).
__device__ __forceinline__ float edge_ex(const float4* __restrict__ a_s,
                                         int e, float4 ad, int myh,
                                         int want, int& src) {
    src = g_esrc[e];
    float4 s = a_s[src];
    float eh = sel4(make_float4(lrelu(s.x + ad.x), lrelu(s.y + ad.y),
                                lrelu(s.z + ad.z), lrelu(s.w + ad.w)), myh);
    float ex = __expf(eh);
    return __shfl_sync(0xffffffffu, ex, want);
}

__device__ __forceinline__ void edge_ex2(const float4* __restrict__ a_s,
                                         int e, float4 ad, int myh,
                                         int w0, int w1, float& ex0, float& ex1, int& src) {
    src = g_esrc[e];
    float4 s = a_s[src];
    float eh = sel4(make_float4(lrelu(s.x + ad.x), lrelu(s.y + ad.y),
                                lrelu(s.z + ad.z), lrelu(s.w + ad.w)), myh);
    float ex = __expf(eh);
    ex0 = __shfl_sync(0xffffffffu, ex, w0);
    ex1 = __shfl_sync(0xffffffffu, ex, w1);
}

// ---------------- init: dtype detect + cnt=1 + alphaA zero ----------------
__global__ void init_detect(const int* __restrict__ ei, const int* __restrict__ eli) {
    int i = blockIdx.x * blockDim.x + threadIdx.x;
    if (i < NNODE) {
        g_cnt[i] = 1;
        g_alpha_sA[i] = make_float4(0, 0, 0, 0);
        g_alpha_dA[i] = make_float4(0, 0, 0, 0);
    }
    if (i == 0) {
        int ok = 1;
        #pragma unroll
        for (int j = 1; j < 64; j += 2) if (ei[j] != 0) { ok = 0; break; }
        g_idx64_ei = ok;
        ok = 1;
        #pragma unroll
        for (int j = 1; j < 64; j += 2) if (eli[j] != 0) { ok = 0; break; }
        g_idx64_eli = ok;
    }
}

// ================= operand splitting (x + all weights, one launch) =========
#define NX4 (NNODE * 384 / 4)
__global__ void split_all(const float* __restrict__ x, const float* __restrict__ W1,
                          const float* __restrict__ W2, const float* __restrict__ W3) {
    int t = blockIdx.x * blockDim.x + threadIdx.x;
    if (t < NX4) {
        long i = (long)t * 4;
        float4 v = *(const float4*)(x + i);
        __nv_bfloat16 h0, h1, h2, h3, l0, l1, l2, l3;
        cvt_split(v.x, h0, l0); cvt_split(v.y, h1, l1);
        cvt_split(v.z, h2, l2); cvt_split(v.w, h3, l3);
        *(__nv_bfloat162*)&g_pAh[i]     = __nv_bfloat162(h0, h1);
        *(__nv_bfloat162*)&g_pAh[i + 2] = __nv_bfloat162(h2, h3);
        *(__nv_bfloat162*)&g_pAl[i]     = __nv_bfloat162(l0, l1);
        *(__nv_bfloat162*)&g_pAl[i + 2] = __nv_bfloat162(l2, l3);
        return;
    }
    int i = t - NX4;
    const float* W; int K, N, off, li;
    if (i < 98304)       { W = W1; K = 384; N = 256; off = 0;      li = i; }
    else if (i < 114688) { W = W2; K = 256; N = 64;  off = 98304;  li = i - 98304; }
    else if (i < 122880) { W = W3; K = 64;  N = 128; off = 114688; li = i - 114688; }
    else return;
    int k = li / N, n = li % N;
    __nv_bfloat16 h, l;
    cvt_split(W[li], h, l);
    g_pBh[off + n * K + k] = h;
    g_pBl[off + n * K + k] = l;
}

// ================= CSR build (parallel scan) =================
__global__ void hist_edges(const void* __restrict__ ei) {
    int e = blockIdx.x * blockDim.x + threadIdx.x;
    if (e >= NEDGE) return;
    int dst = load_idx(ei, g_idx64_ei, (long long)NEDGE + e);
    atomicAdd(&g_cnt[dst], 1);
}

__global__ void csr_s1() {
    __shared__ int ws[32];
    int i = blockIdx.x * 1024 + threadIdx.x;
    int lane = threadIdx.x & 31, wid = threadIdx.x >> 5;
    int v = (i < NNODE) ? g_cnt[i] : 0;
    #pragma unroll
    for (int o = 16; o; o >>= 1) v += __shfl_xor_sync(0xffffffffu, v, o);
    if (lane == 0) ws[wid] = v;
    __syncthreads();
    if (threadIdx.x < 32) {
        int s = ws[threadIdx.x];
        #pragma unroll
        for (int o = 16; o; o >>= 1) s += __shfl_xor_sync(0xffffffffu, s, o);
        if (threadIdx.x == 0) g_bsum[blockIdx.x] = s;
    }
}

__global__ void csr_s2() {
    __shared__ int w0tot;
    int t = threadIdx.x;
    int lane = t & 31, w = t >> 5;
    int v = (t < NBLK) ? g_bsum[t] : 0;
    int x = v;
    #pragma unroll
    for (int o = 1; o < 32; o <<= 1) {
        int y = __shfl_up_sync(0xffffffffu, x, o);
        if (lane >= o) x += y;
    }
    if (t == 31) w0tot = x;
    __syncthreads();
    if (w == 1) x += w0tot;
    if (t < NBLK) g_boff[t] = x - v;
}

__global__ void csr_s3() {
    __shared__ int ws[32];
    int i = blockIdx.x * 1024 + threadIdx.x;
    int lane = threadIdx.x & 31, wid = threadIdx.x >> 5;
    int v = (i < NNODE) ? g_cnt[i] : 0;
    int x = v;
    #pragma unroll
    for (int o = 1; o < 32; o <<= 1) {
        int y = __shfl_up_sync(0xffffffffu, x, o);
        if (lane >= o) x += y;
    }
    if (lane == 31) ws[wid] = x;
    __syncthreads();
    if (wid == 0) {
        int s = ws[lane];
        #pragma unroll
        for (int o = 1; o < 32; o <<= 1) {
            int y = __shfl_up_sync(0xffffffffu, s, o);
            if (lane >= o) s += y;
        }
        ws[lane] = s;
    }
    __syncthreads();
    int ex = x - v + (wid ? ws[wid - 1] : 0) + g_boff[blockIdx.x];
    if (i < NNODE) {
        g_rowoff[i] = ex;
        g_cursor[i] = ex + 1;
        g_esrc[ex] = i;
        if (i == NNODE - 1) g_rowoff[NNODE] = ex + v;
    }
}

__global__ void scatter_edges(const void* __restrict__ ei) {
    int e = blockIdx.x * blockDim.x + threadIdx.x;
    if (e >= NEDGE) return;
    int use64 = g_idx64_ei;
    int src = load_idx(ei, use64, e);
    int dst = load_idx(ei, use64, (long long)NEDGE + e);
    int pos = atomicAdd(&g_cursor[dst], 1);
    g_esrc[pos] = src;
}

// ======= split-bf16 mma.sync GEMM, 3-stage cp.async + fused alpha =========
#define BKP 40
#define A_SZ (128 * BKP)
#define B_SZ (64 * BKP)
#define STG  (2 * A_SZ + 2 * B_SZ)
#define NSTAGE 3
#define GEMM_SMEM (NSTAGE * STG * 2)   // 92160 bytes

__device__ __forceinline__ void mma16816(float* c, const uint32_t* a, const uint32_t* b) {
    asm volatile(
        "mma.sync.aligned.m16n8k16.row.col.f32.bf16.bf16.f32 "
        "{%0,%1,%2,%3}, {%4,%5,%6,%7}, {%8,%9}, {%0,%1,%2,%3};\n"
        : "+f"(c[0]), "+f"(c[1]), "+f"(c[2]), "+f"(c[3])
        : "r"(a[0]), "r"(a[1]), "r"(a[2]), "r"(a[3]), "r"(b[0]), "r"(b[1]));
}

__global__ __launch_bounds__(256) void gemm_tc(const __nv_bfloat16* __restrict__ Ah,
                                               const __nv_bfloat16* __restrict__ Al,
                                               const __nv_bfloat16* __restrict__ Bth,
                                               const __nv_bfloat16* __restrict__ Btl,
                                               float* __restrict__ C,
                                               const float* __restrict__ a_s,
                                               const float* __restrict__ a_d,
                                               float* __restrict__ alpha_s_out,
                                               float* __restrict__ alpha_d_out,
                                               int M, int N, int K, int Ch) {
    extern __shared__ __nv_bfloat16 sm[];
    const int tid  = threadIdx.x;
    const int lane = tid & 31;
    const int warp = tid >> 5;
    const int wm   = warp & 3;
    const int wn   = warp >> 2;
    const int tr   = lane >> 2;
    const int tc   = lane & 3;
    const int row0 = blockIdx.y * 128;
    const int col0 = blockIdx.x * 64;
    const int KT   = K / 32;

    float acc[2][4][4] = {};

    auto stage_load = [&](int s, int kt) {
        if (kt < KT) {
            int k0 = kt * 32;
            __nv_bfloat16* sAh = sm + s * STG;
            __nv_bfloat16* sAl = sAh + A_SZ;
            __nv_bfloat16* sBh = sAl + A_SZ;
            __nv_bfloat16* sBl = sBh + B_SZ;
            #pragma unroll
            for (int i = 0; i < 2; i++) {
                int id = tid + i * 256;
                int row = id >> 2, c = id & 3;
                long gofs = (long)(row0 + row) * K + k0 + c * 8;
                cp16(sAh + row * BKP + c * 8, Ah + gofs);
                cp16(sAl + row * BKP + c * 8, Al + gofs);
            }
            {
                int n = tid >> 2, c = tid & 3;
                long gofs = (long)(col0 + n) * K + k0 + c * 8;
                cp16(sBh + n * BKP + c * 8, Bth + gofs);
                cp16(sBl + n * BKP + c * 8, Btl + gofs);
            }
        }
        asm volatile("cp.async.commit_group;\n" ::: "memory");
    };

    auto compute = [&](int s) {
        const __nv_bfloat16* sAh = sm + s * STG;
        const __nv_bfloat16* sAl = sAh + A_SZ;
        const __nv_bfloat16* sBh = sAl + A_SZ;
        const __nv_bfloat16* sBl = sBh + B_SZ;
        #pragma unroll
        for (int ks = 0; ks < 32; ks += 16) {
            uint32_t ah[2][4], al[2][4], bh[4][2], bl[4][2];
            #pragma unroll
            for (int f = 0; f < 2; f++) {
                int r = wm * 32 + f * 16 + tr;
                int kk = ks + tc * 2;
                ah[f][0] = *(const uint32_t*)&sAh[r * BKP + kk];
                ah[f][1] = *(const uint32_t*)&sAh[(r + 8) * BKP + kk];
                ah[f][2] = *(const uint32_t*)&sAh[r * BKP + kk + 8];
                ah[f][3] = *(const uint32_t*)&sAh[(r + 8) * BKP + kk + 8];
                al[f][0] = *(const uint32_t*)&sAl[r * BKP + kk];
                al[f][1] = *(const uint32_t*)&sAl[(r + 8) * BKP + kk];
                al[f][2] = *(const uint32_t*)&sAl[r * BKP + kk + 8];
                al[f][3] = *(const uint32_t*)&sAl[(r + 8) * BKP + kk + 8];
            }
            #pragma unroll
            for (int g = 0; g < 4; g++) {
                int n = wn * 32 + g * 8 + tr;
                int kk = ks + tc * 2;
                bh[g][0] = *(const uint32_t*)&sBh[n * BKP + kk];
                bh[g][1] = *(const uint32_t*)&sBh[n * BKP + kk + 8];
                bl[g][0] = *(const uint32_t*)&sBl[n * BKP + kk];
                bl[g][1] = *(const uint32_t*)&sBl[n * BKP + kk + 8];
            }
            #pragma unroll
            for (int f = 0; f < 2; f++)
                #pragma unroll
                for (int g = 0; g < 4; g++) {
                    mma16816(acc[f][g], ah[f], bh[g]);
                    mma16816(acc[f][g], ah[f], bl[g]);
                    mma16816(acc[f][g], al[f], bh[g]);
                }
        }
    };

    stage_load(0, 0);
    stage_load(1, 1);
    for (int kt = 0; kt < KT; kt++) {
        asm volatile("cp.async.wait_group 1;\n" ::: "memory");
        __syncthreads();
        stage_load((kt + 2) % NSTAGE, kt + 2);
        compute(kt % NSTAGE);
    }

    // ---- store C ----
    #pragma unroll
    for (int f = 0; f < 2; f++) {
        int r = row0 + wm * 32 + f * 16 + tr;
        #pragma unroll
        for (int g = 0; g < 4; g++) {
            int c = col0 + wn * 32 + g * 8 + tc * 2;
            if (r < M)
                *(float2*)&C[(long)r * N + c] = make_float2(acc[f][g][0], acc[f][g][1]);
            if (r + 8 < M)
                *(float2*)&C[(long)(r + 8) * N + c] = make_float2(acc[f][g][2], acc[f][g][3]);
        }
    }

    // ---- fused alpha epilogue ----
    float asv[8], adv[8];
    #pragma unroll
    for (int g = 0; g < 4; g++) {
        int colg = col0 + wn * 32 + g * 8 + tc * 2;
        asv[g * 2] = __ldg(&a_s[colg]); asv[g * 2 + 1] = __ldg(&a_s[colg + 1]);
        adv[g * 2] = __ldg(&a_d[colg]); adv[g * 2 + 1] = __ldg(&a_d[colg + 1]);
    }
    const int hlo = (col0 + wn * 32) / Ch;
    const bool two_heads = (Ch == 16);
    #pragma unroll
    for (int f = 0; f < 2; f++) {
        #pragma unroll
        for (int half = 0; half < 2; half++) {
            int row = row0 + wm * 32 + f * 16 + tr + half * 8;
            float psg[4], pdg[4];
            #pragma unroll
            for (int g = 0; g < 4; g++) {
                float a0 = acc[f][g][half * 2], a1 = acc[f][g][half * 2 + 1];
                psg[g] = a0 * asv[g * 2] + a1 * asv[g * 2 + 1];
                pdg[g] = a0 * adv[g * 2] + a1 * adv[g * 2 + 1];
            }
            float s0 = psg[0] + psg[1], s1 = psg[2] + psg[3];
            float d0 = pdg[0] + pdg[1], d1 = pdg[2] + pdg[3];
            #pragma unroll
            for (int o = 1; o <= 2; o <<= 1) {
                s0 += __shfl_xor_sync(0xffffffffu, s0, o);
                s1 += __shfl_xor_sync(0xffffffffu, s1, o);
                d0 += __shfl_xor_sync(0xffffffffu, d0, o);
                d1 += __shfl_xor_sync(0xffffffffu, d1, o);
            }
            if (tc == 0 && row < M) {
                if (two_heads) {
                    atomicAdd(&alpha_s_out[row * 4 + hlo], s0);
                    atomicAdd(&alpha_s_out[row * 4 + hlo + 1], s1);
                    atomicAdd(&alpha_d_out[row * 4 + hlo], d0);
                    atomicAdd(&alpha_d_out[row * 4 + hlo + 1], d1);
                } else {
                    atomicAdd(&alpha_s_out[row * 4 + hlo], s0 + s1);
                    atomicAdd(&alpha_d_out[row * 4 + hlo], d0 + d1);
                }
            }
        }
    }
}

// ========== fused softmax+aggregate kernels (single pass, no max) ==========

// Layer 1: F=256, C=64 -> elu(out+bias) -> split bf16 planes.
__global__ void gat_agg_l1(const float* __restrict__ bias) {
    int dstN = (blockIdx.x * blockDim.x + threadIdx.x) >> 5;
    int lane = threadIdx.x & 31;
    if (dstN >= NNODE) return;
    int r0 = g_rowoff[dstN], r1 = g_rowoff[dstN + 1];
    const float4* a_s = g_alpha_sA;
    float4 ad = g_alpha_dA[dstN];

    const int myh = lane & 3;
    const int hd0 = lane >> 4;
    const int hd1 = 2 + (lane >> 4);
    float4 acc0 = make_float4(0, 0, 0, 0), acc1 = make_float4(0, 0, 0, 0);
    float den0 = 0.f, den1 = 0.f;

    int e = r0;
    for (; e + 1 < r1; e += 2) {
        int sA, sB; float xA0, xA1, xB0, xB1;
        edge_ex2(a_s, e,     ad, myh, hd0, hd1, xA0, xA1, sA);
        edge_ex2(a_s, e + 1, ad, myh, hd0, hd1, xB0, xB1, sB);
        const float4* hA = (const float4*)(g_h + (long)sA * 256);
        const float4* hB = (const float4*)(g_h + (long)sB * 256);
        float4 vA0 = hA[lane], vA1 = hA[lane + 32];
        float4 vB0 = hB[lane], vB1 = hB[lane + 32];
        acc0.x += vA0.x * xA0 + vB0.x * xB0;  acc0.y += vA0.y * xA0 + vB0.y * xB0;
        acc0.z += vA0.z * xA0 + vB0.z * xB0;  acc0.w += vA0.w * xA0 + vB0.w * xB0;
        acc1.x += vA1.x * xA1 + vB1.x * xB1;  acc1.y += vA1.y * xA1 + vB1.y * xB1;
        acc1.z += vA1.z * xA1 + vB1.z * xB1;  acc1.w += vA1.w * xA1 + vB1.w * xB1;
        den0 += xA0 + xB0;  den1 += xA1 + xB1;
    }
    if (e < r1) {
        int s; float x0, x1;
        edge_ex2(a_s, e, ad, myh, hd0, hd1, x0, x1, s);
        const float4* hp = (const float4*)(g_h + (long)s * 256);
        float4 v0 = hp[lane], v1 = hp[lane + 32];
        acc0.x += v0.x * x0; acc0.y += v0.y * x0; acc0.z += v0.z * x0; acc0.w += v0.w * x0;
        acc1.x += v1.x * x1; acc1.y += v1.y * x1; acc1.z += v1.z * x1; acc1.w += v1.w * x1;
        den0 += x0; den1 += x1;
    }

    float iv0 = 1.f / (den0 + 1e-16f), iv1 = 1.f / (den1 + 1e-16f);
    #pragma unroll
    for (int c = 0; c < 2; c++) {
        int f = lane * 4 + c * 128;
        float iv = c == 0 ? iv0 : iv1;
        float4 r = c == 0 ? acc0 : acc1;
        r.x = r.x * iv + bias[f];     r.y = r.y * iv + bias[f + 1];
        r.z = r.z * iv + bias[f + 2]; r.w = r.w * iv + bias[f + 3];
        r.x = r.x > 0.f ? r.x : expm1f(r.x);
        r.y = r.y > 0.f ? r.y : expm1f(r.y);
        r.z = r.z > 0.f ? r.z : expm1f(r.z);
        r.w = r.w > 0.f ? r.w : expm1f(r.w);
        __nv_bfloat16 h0, h1, h2, h3, l0, l1, l2, l3;
        cvt_split(r.x, h0, l0); cvt_split(r.y, h1, l1);
        cvt_split(r.z, h2, l2); cvt_split(r.w, h3, l3);
        long o = (long)dstN * 256 + f;
        *(__nv_bfloat162*)&g_pAh[o]     = __nv_bfloat162(h0, h1);
        *(__nv_bfloat162*)&g_pAh[o + 2] = __nv_bfloat162(h2, h3);
        *(__nv_bfloat162*)&g_pAl[o]     = __nv_bfloat162(l0, l1);
        *(__nv_bfloat162*)&g_pAl[o + 2] = __nv_bfloat162(l2, l3);
    }
    if (lane == 0) {
        g_alpha_sB[dstN] = make_float4(0, 0, 0, 0);
        g_alpha_dB[dstN] = make_float4(0, 0, 0, 0);
    }
}

// Layer 2: F=64, C=16 -> elu(out+bias) -> split bf16 planes.
__global__ void gat_agg_l2(const float* __restrict__ bias) {
    int dstN = (blockIdx.x * blockDim.x + threadIdx.x) >> 5;
    int lane = threadIdx.x & 31;
    if (dstN >= NNODE) return;
    int r0 = g_rowoff[dstN], r1 = g_rowoff[dstN + 1];
    const float4* a_s = g_alpha_sB;
    float4 ad = g_alpha_dB[dstN];

    const int myh = lane & 3;
    const int f = lane * 2;
    const int hd = lane >> 3;
    float a0 = 0.f, a1 = 0.f, den = 0.f;

    int e = r0;
    for (; e + 1 < r1; e += 2) {
        int sA, sB;
        float xA = edge_ex(a_s, e,     ad, myh, hd, sA);
        float xB = edge_ex(a_s, e + 1, ad, myh, hd, sB);
        float2 hA = *(const float2*)(g_h + (long)sA * 64 + f);
        float2 hB = *(const float2*)(g_h + (long)sB * 64 + f);
        a0 += hA.x * xA + hB.x * xB;
        a1 += hA.y * xA + hB.y * xB;
        den += xA + xB;
    }
    if (e < r1) {
        int s;
        float x = edge_ex(a_s, e, ad, myh, hd, s);
        float2 hv = *(const float2*)(g_h + (long)s * 64 + f);
        a0 += hv.x * x; a1 += hv.y * x; den += x;
    }

    float iv = 1.f / (den + 1e-16f);
    a0 = a0 * iv + bias[f];
    a1 = a1 * iv + bias[f + 1];
    a0 = a0 > 0.f ? a0 : expm1f(a0);
    a1 = a1 > 0.f ? a1 : expm1f(a1);
    __nv_bfloat16 h0, h1, l0, l1;
    cvt_split(a0, h0, l0); cvt_split(a1, h1, l1);
    *(__nv_bfloat162*)&g_pAh[(long)dstN * 64 + f] = __nv_bfloat162(h0, h1);
    *(__nv_bfloat162*)&g_pAl[(long)dstN * 64 + f] = __nv_bfloat162(l0, l1);
    if (lane == 0) {
        g_alpha_sA[dstN] = make_float4(0, 0, 0, 0);
        g_alpha_dA[dstN] = make_float4(0, 0, 0, 0);
    }
}

// Layer 3: F=128, C=32, fused head-mean + b3 -> g_z.
__global__ void gat_agg_l3(const float* __restrict__ b3) {
    int dstN = (blockIdx.x * blockDim.x + threadIdx.x) >> 5;
    int lane = threadIdx.x & 31;
    if (dstN >= NNODE) return;
    int r0 = g_rowoff[dstN], r1 = g_rowoff[dstN + 1];
    const float4* a_s = g_alpha_sA;
    float4 ad = g_alpha_dA[dstN];

    const int myh = lane & 3;
    const int hd = lane >> 3;
    float4 acc = make_float4(0, 0, 0, 0);
    float den = 0.f;

    int e = r0;
    for (; e + 1 < r1; e += 2) {
        int sA, sB;
        float xA = edge_ex(a_s, e,     ad, myh, hd, sA);
        float xB = edge_ex(a_s, e + 1, ad, myh, hd, sB);
        float4 vA = ((const float4*)(g_h + (long)sA * 128))[lane];
        float4 vB = ((const float4*)(g_h + (long)sB * 128))[lane];
        acc.x += vA.x * xA + vB.x * xB;  acc.y += vA.y * xA + vB.y * xB;
        acc.z += vA.z * xA + vB.z * xB;  acc.w += vA.w * xA + vB.w * xB;
        den += xA + xB;
    }
    if (e < r1) {
        int s;
        float x = edge_ex(a_s, e, ad, myh, hd, s);
        float4 v = ((const float4*)(g_h + (long)s * 128))[lane];
        acc.x += v.x * x; acc.y += v.y * x; acc.z += v.z * x; acc.w += v.w * x;
        den += x;
    }

    float iv = 1.f / (den + 1e-16f);
    acc.x *= iv; acc.y *= iv; acc.z *= iv; acc.w *= iv;
    #pragma unroll
    for (int o = 8; o <= 16; o <<= 1) {
        acc.x += __shfl_xor_sync(0xffffffffu, acc.x, o);
        acc.y += __shfl_xor_sync(0xffffffffu, acc.y, o);
        acc.z += __shfl_xor_sync(0xffffffffu, acc.z, o);
        acc.w += __shfl_xor_sync(0xffffffffu, acc.w, o);
    }
    if (lane < 8) {
        int c = lane * 4;
        float4 z = make_float4(0.25f * acc.x + b3[c],     0.25f * acc.y + b3[c + 1],
                               0.25f * acc.z + b3[c + 2], 0.25f * acc.w + b3[c + 3]);
        *(float4*)&g_z[(long)dstN * 32 + c] = z;
    }
}

// ---------------- logits: 8 lanes per candidate edge (4 edges/warp) ----------
__global__ void dot_kernel(const void* __restrict__ eli, float* __restrict__ out) {
    int gw = (blockIdx.x * blockDim.x + threadIdx.x) >> 5;
    int lane = threadIdx.x & 31;
    int sub = lane >> 3, sl = lane & 7;
    int w = gw * 4 + sub;
    if (w >= ECAND) return;   // ECAND % 4 == 0: whole warps exit together
    int use64 = g_idx64_eli;
    int s = load_idx(eli, use64, w);
    int d = load_idx(eli, use64, (long long)ECAND + w);
    float4 a = ((const float4*)(g_z + (long)s * 32))[sl];
    float4 b = ((const float4*)(g_z + (long)d * 32))[sl];
    float p = a.x * b.x + a.y * b.y + a.z * b.z + a.w * b.w;
    #pragma unroll
    for (int o = 1; o <= 4; o <<= 1) p += __shfl_xor_sync(0xffffffffu, p, o);
    if (sl == 0) out[w] = p;
}

// ---------------- host launch ----------------
extern "C" void kernel_launch(void* const* d_in, const int* in_sizes, int n_in,
                              void* d_out, int out_size) {
    const float* x   = (const float*)d_in[0];
    const void*  ei  = d_in[1];
    const void*  eli = d_in[2];
    const float* W1  = (const float*)d_in[3];
    const float* a1s = (const float*)d_in[4];
    const float* a1d = (const float*)d_in[5];
    const float* b1  = (const float*)d_in[6];
    const float* W2  = (const float*)d_in[7];
    const float* a2s = (const float*)d_in[8];
    const float* a2d = (const float*)d_in[9];
    const float* b2  = (const float*)d_in[10];
    const float* W3  = (const float*)d_in[11];
    const float* a3s = (const float*)d_in[12];
    const float* a3d = (const float*)d_in[13];
    const float* b3  = (const float*)d_in[14];
    float* out = (float*)d_out;

    float* p_h;
    cudaGetSymbolAddress((void**)&p_h, g_h);
    __nv_bfloat16 *p_Ah, *p_Al, *p_Bh, *p_Bl;
    cudaGetSymbolAddress((void**)&p_Ah, g_pAh);
    cudaGetSymbolAddress((void**)&p_Al, g_pAl);
    cudaGetSymbolAddress((void**)&p_Bh, g_pBh);
    cudaGetSymbolAddress((void**)&p_Bl, g_pBl);
    float *p_asA, *p_adA, *p_asB, *p_adB;
    cudaGetSymbolAddress((void**)&p_asA, g_alpha_sA);
    cudaGetSymbolAddress((void**)&p_adA, g_alpha_dA);
    cudaGetSymbolAddress((void**)&p_asB, g_alpha_sB);
    cudaGetSymbolAddress((void**)&p_adB, g_alpha_dB);

    static cudaStream_t sB = nullptr;
    static cudaEvent_t evFork = nullptr, evInit = nullptr, evJoin = nullptr;
    static bool attr_done = false;
    if (!attr_done) {
        cudaFuncSetAttribute(gemm_tc, cudaFuncAttributeMaxDynamicSharedMemorySize, GEMM_SMEM);
        cudaStreamCreateWithFlags(&sB, cudaStreamNonBlocking);
        cudaEventCreateWithFlags(&evFork, cudaEventDisableTiming);
        cudaEventCreateWithFlags(&evInit, cudaEventDisableTiming);
        cudaEventCreateWithFlags(&evJoin, cudaEventDisableTiming);
        attr_done = true;
    }

    const int TB = 256;
    const int nodeWarpBlocks = (NNODE * 32 + TB - 1) / TB;
    const int MB = (NNODE + 127) / 128;

    // ---- fork at t=0: side stream joins capture via event on stream 0 ----
    cudaEventRecord(evFork, 0);
    cudaStreamWaitEvent(sB, evFork, 0);

    // ---- side stream: init (alphaA zero + dtype flags + cnt) then CSR ----
    init_detect<<<(NNODE + TB - 1) / TB, TB, 0, sB>>>((const int*)ei, (const int*)eli);
    cudaEventRecord(evInit, sB);
    hist_edges<<<(NEDGE + TB - 1) / TB, TB, 0, sB>>>(ei);
    csr_s1<<<NBLK, 1024, 0, sB>>>();
    csr_s2<<<1, 64, 0, sB>>>();
    csr_s3<<<NBLK, 1024, 0, sB>>>();
    scatter_edges<<<(NEDGE + TB - 1) / TB, TB, 0, sB>>>(ei);
    cudaEventRecord(evJoin, sB);

    // ---- main stream: split starts at t=0 (depends only on inputs) ----
    split_all<<<(NX4 + 122880 + TB - 1) / TB, TB>>>(x, W1, W2, W3);
    cudaStreamWaitEvent(0, evInit, 0);   // gemm1 accumulates into alphaA (zeroed by init)
    gemm_tc<<<dim3(4, MB), 256, GEMM_SMEM>>>(p_Ah, p_Al, p_Bh, p_Bl, p_h,
                                             a1s, a1d, p_asA, p_adA, NNODE, 256, 384, 64);

    // ---- join: aggregates need the CSR ----
    cudaStreamWaitEvent(0, evJoin, 0);
    gat_agg_l1<<<nodeWarpBlocks, TB>>>(b1);

    // ---- Layer 2 ----
    gemm_tc<<<dim3(1, MB), 256, GEMM_SMEM>>>(p_Ah, p_Al, p_Bh + 98304, p_Bl + 98304, p_h,
                                             a2s, a2d, p_asB, p_adB, NNODE, 64, 256, 16);
    gat_agg_l2<<<nodeWarpBlocks, TB>>>(b2);

    // ---- Layer 3 ----
    gemm_tc<<<dim3(2, MB), 256, GEMM_SMEM>>>(p_Ah, p_Al, p_Bh + 114688, p_Bl + 114688, p_h,
                                             a3s, a3d, p_asA, p_adA, NNODE, 128, 64, 32);
    gat_agg_l3<<<nodeWarpBlocks, TB>>>(b3);

    // ---- Candidate-edge logits (4 edges per warp) ----
    dot_kernel<<<(ECAND / 4 * 32 + TB - 1) / TB, TB>>>(eli, out);
}

// round 16
// speedup vs baseline: 1.0967x; 1.0551x over previous
#include <cuda_runtime.h>
#include <cuda_bf16.h>
#include <cuda_fp16.h>
#include <math.h>
#include <stdint.h>

#define NNODE   50000
#define NEDGE   800000
#define ET      850000      // NEDGE + NNODE self loops
#define ECAND   200000
#define MPAD    50048       // ceil(NNODE/128)*128
#define KMAX    384
#define NBLK    49          // ceil(NNODE/1024)

// ---------------- scratch (device globals; no allocation) ----------------
__device__ __align__(16) __nv_bfloat16 g_pAh[MPAD * KMAX];  // A hi plane
__device__ __align__(16) __nv_bfloat16 g_pAl[MPAD * KMAX];  // A lo plane
// packed W planes [N][K]: L1 @0 (384*256), L2 @98304 (256*64), L3 @114688 (64*128)
__device__ __align__(16) __nv_bfloat16 g_pBh[122880];
__device__ __align__(16) __nv_bfloat16 g_pBl[122880];
__device__ __align__(16) __half g_h[NNODE * 256];           // GEMM output (fp16)
// ping-pong alpha buffers
__device__ float4 g_alpha_sA[NNODE];
__device__ float4 g_alpha_dA[NNODE];
__device__ float4 g_alpha_sB[NNODE];
__device__ float4 g_alpha_dB[NNODE];
__device__ int    g_esrc[ET];
__device__ int    g_rowoff[NNODE + 1];
__device__ int    g_cnt[NNODE];
__device__ int    g_cursor[NNODE];
__device__ int    g_bsum[64];
__device__ int    g_boff[64];
__device__ __align__(16) float g_z[NNODE * 32];
__device__ int    g_idx64_ei;
__device__ int    g_idx64_eli;

// ---------------- helpers ----------------
__device__ __forceinline__ float lrelu(float v) { return v > 0.f ? v : 0.2f * v; }

__device__ __forceinline__ float sel4(float4 v, int h) {
    return h < 2 ? (h == 0 ? v.x : v.y) : (h == 2 ? v.z : v.w);
}

__device__ __forceinline__ int load_idx(const void* p, int use64, long long pos) {
    return use64 ? (int)((const long long*)p)[pos] : ((const int*)p)[pos];
}

__device__ __forceinline__ void cvt_split(float v, __nv_bfloat16& h, __nv_bfloat16& l) {
    h = __float2bfloat16(v);
    l = __float2bfloat16(v - __bfloat162float(h));
}

__device__ __forceinline__ void cp16(const void* s, const void* g) {
    uint32_t sa = (uint32_t)__cvta_generic_to_shared(s);
    asm volatile("cp.async.cg.shared.global [%0], [%1], 16;\n" :: "r"(sa), "l"(g));
}

// load 4 consecutive halves -> float4 (8-byte vectorized)
__device__ __forceinline__ float4 load4h(const __half* p) {
    uint2 u = *(const uint2*)p;
    float2 f01 = __half22float2(*(__half2*)&u.x);
    float2 f23 = __half22float2(*(__half2*)&u.y);
    return make_float4(f01.x, f01.y, f23.x, f23.y);
}

// per-edge: ex for one head, computed warp-wide (lane L evals head L&3),
// fetched per-lane via shfl. No max subtraction (softmax is shift-invariant;
// |e| <~ 15 here so exp stays far from fp32 limits).
__device__ __forceinline__ float edge_ex(const float4* __restrict__ a_s,
                                         int e, float4 ad, int myh,
                                         int want, int& src) {
    src = g_esrc[e];
    float4 s = a_s[src];
    float eh = sel4(make_float4(lrelu(s.x + ad.x), lrelu(s.y + ad.y),
                                lrelu(s.z + ad.z), lrelu(s.w + ad.w)), myh);
    float ex = __expf(eh);
    return __shfl_sync(0xffffffffu, ex, want);
}

__device__ __forceinline__ void edge_ex2(const float4* __restrict__ a_s,
                                         int e, float4 ad, int myh,
                                         int w0, int w1, float& ex0, float& ex1, int& src) {
    src = g_esrc[e];
    float4 s = a_s[src];
    float eh = sel4(make_float4(lrelu(s.x + ad.x), lrelu(s.y + ad.y),
                                lrelu(s.z + ad.z), lrelu(s.w + ad.w)), myh);
    float ex = __expf(eh);
    ex0 = __shfl_sync(0xffffffffu, ex, w0);
    ex1 = __shfl_sync(0xffffffffu, ex, w1);
}

// ---------------- init: dtype detect + cnt=1 + alphaA zero ----------------
__global__ void init_detect(const int* __restrict__ ei, const int* __restrict__ eli) {
    int i = blockIdx.x * blockDim.x + threadIdx.x;
    if (i < NNODE) {
        g_cnt[i] = 1;
        g_alpha_sA[i] = make_float4(0, 0, 0, 0);
        g_alpha_dA[i] = make_float4(0, 0, 0, 0);
    }
    if (i == 0) {
        int ok = 1;
        #pragma unroll
        for (int j = 1; j < 64; j += 2) if (ei[j] != 0) { ok = 0; break; }
        g_idx64_ei = ok;
        ok = 1;
        #pragma unroll
        for (int j = 1; j < 64; j += 2) if (eli[j] != 0) { ok = 0; break; }
        g_idx64_eli = ok;
    }
}

// ================= operand splitting (x + all weights, one launch) =========
#define NX4 (NNODE * 384 / 4)
__global__ void split_all(const float* __restrict__ x, const float* __restrict__ W1,
                          const float* __restrict__ W2, const float* __restrict__ W3) {
    int t = blockIdx.x * blockDim.x + threadIdx.x;
    if (t < NX4) {
        long i = (long)t * 4;
        float4 v = *(const float4*)(x + i);
        __nv_bfloat16 h0, h1, h2, h3, l0, l1, l2, l3;
        cvt_split(v.x, h0, l0); cvt_split(v.y, h1, l1);
        cvt_split(v.z, h2, l2); cvt_split(v.w, h3, l3);
        *(__nv_bfloat162*)&g_pAh[i]     = __nv_bfloat162(h0, h1);
        *(__nv_bfloat162*)&g_pAh[i + 2] = __nv_bfloat162(h2, h3);
        *(__nv_bfloat162*)&g_pAl[i]     = __nv_bfloat162(l0, l1);
        *(__nv_bfloat162*)&g_pAl[i + 2] = __nv_bfloat162(l2, l3);
        return;
    }
    int i = t - NX4;
    const float* W; int K, N, off, li;
    if (i < 98304)       { W = W1; K = 384; N = 256; off = 0;      li = i; }
    else if (i < 114688) { W = W2; K = 256; N = 64;  off = 98304;  li = i - 98304; }
    else if (i < 122880) { W = W3; K = 64;  N = 128; off = 114688; li = i - 114688; }
    else return;
    int k = li / N, n = li % N;
    __nv_bfloat16 h, l;
    cvt_split(W[li], h, l);
    g_pBh[off + n * K + k] = h;
    g_pBl[off + n * K + k] = l;
}

// ================= CSR build (parallel scan) =================
__global__ void hist_edges(const void* __restrict__ ei) {
    int e = blockIdx.x * blockDim.x + threadIdx.x;
    if (e >= NEDGE) return;
    int dst = load_idx(ei, g_idx64_ei, (long long)NEDGE + e);
    atomicAdd(&g_cnt[dst], 1);
}

__global__ void csr_s1() {
    __shared__ int ws[32];
    int i = blockIdx.x * 1024 + threadIdx.x;
    int lane = threadIdx.x & 31, wid = threadIdx.x >> 5;
    int v = (i < NNODE) ? g_cnt[i] : 0;
    #pragma unroll
    for (int o = 16; o; o >>= 1) v += __shfl_xor_sync(0xffffffffu, v, o);
    if (lane == 0) ws[wid] = v;
    __syncthreads();
    if (threadIdx.x < 32) {
        int s = ws[threadIdx.x];
        #pragma unroll
        for (int o = 16; o; o >>= 1) s += __shfl_xor_sync(0xffffffffu, s, o);
        if (threadIdx.x == 0) g_bsum[blockIdx.x] = s;
    }
}

__global__ void csr_s2() {
    __shared__ int w0tot;
    int t = threadIdx.x;
    int lane = t & 31, w = t >> 5;
    int v = (t < NBLK) ? g_bsum[t] : 0;
    int x = v;
    #pragma unroll
    for (int o = 1; o < 32; o <<= 1) {
        int y = __shfl_up_sync(0xffffffffu, x, o);
        if (lane >= o) x += y;
    }
    if (t == 31) w0tot = x;
    __syncthreads();
    if (w == 1) x += w0tot;
    if (t < NBLK) g_boff[t] = x - v;
}

__global__ void csr_s3() {
    __shared__ int ws[32];
    int i = blockIdx.x * 1024 + threadIdx.x;
    int lane = threadIdx.x & 31, wid = threadIdx.x >> 5;
    int v = (i < NNODE) ? g_cnt[i] : 0;
    int x = v;
    #pragma unroll
    for (int o = 1; o < 32; o <<= 1) {
        int y = __shfl_up_sync(0xffffffffu, x, o);
        if (lane >= o) x += y;
    }
    if (lane == 31) ws[wid] = x;
    __syncthreads();
    if (wid == 0) {
        int s = ws[lane];
        #pragma unroll
        for (int o = 1; o < 32; o <<= 1) {
            int y = __shfl_up_sync(0xffffffffu, s, o);
            if (lane >= o) s += y;
        }
        ws[lane] = s;
    }
    __syncthreads();
    int ex = x - v + (wid ? ws[wid - 1] : 0) + g_boff[blockIdx.x];
    if (i < NNODE) {
        g_rowoff[i] = ex;
        g_cursor[i] = ex + 1;
        g_esrc[ex] = i;
        if (i == NNODE - 1) g_rowoff[NNODE] = ex + v;
    }
}

__global__ void scatter_edges(const void* __restrict__ ei) {
    int e = blockIdx.x * blockDim.x + threadIdx.x;
    if (e >= NEDGE) return;
    int use64 = g_idx64_ei;
    int src = load_idx(ei, use64, e);
    int dst = load_idx(ei, use64, (long long)NEDGE + e);
    int pos = atomicAdd(&g_cursor[dst], 1);
    g_esrc[pos] = src;
}

// ======= split-bf16 mma.sync GEMM, 3-stage cp.async + fused alpha =========
#define BKP 40
#define A_SZ (128 * BKP)
#define B_SZ (64 * BKP)
#define STG  (2 * A_SZ + 2 * B_SZ)
#define NSTAGE 3
#define GEMM_SMEM (NSTAGE * STG * 2)   // 92160 bytes

__device__ __forceinline__ void mma16816(float* c, const uint32_t* a, const uint32_t* b) {
    asm volatile(
        "mma.sync.aligned.m16n8k16.row.col.f32.bf16.bf16.f32 "
        "{%0,%1,%2,%3}, {%4,%5,%6,%7}, {%8,%9}, {%0,%1,%2,%3};\n"
        : "+f"(c[0]), "+f"(c[1]), "+f"(c[2]), "+f"(c[3])
        : "r"(a[0]), "r"(a[1]), "r"(a[2]), "r"(a[3]), "r"(b[0]), "r"(b[1]));
}

__global__ __launch_bounds__(256) void gemm_tc(const __nv_bfloat16* __restrict__ Ah,
                                               const __nv_bfloat16* __restrict__ Al,
                                               const __nv_bfloat16* __restrict__ Bth,
                                               const __nv_bfloat16* __restrict__ Btl,
                                               __half* __restrict__ C,
                                               const float* __restrict__ a_s,
                                               const float* __restrict__ a_d,
                                               float* __restrict__ alpha_s_out,
                                               float* __restrict__ alpha_d_out,
                                               int M, int N, int K, int Ch) {
    extern __shared__ __nv_bfloat16 sm[];
    const int tid  = threadIdx.x;
    const int lane = tid & 31;
    const int warp = tid >> 5;
    const int wm   = warp & 3;
    const int wn   = warp >> 2;
    const int tr   = lane >> 2;
    const int tc   = lane & 3;
    const int row0 = blockIdx.y * 128;
    const int col0 = blockIdx.x * 64;
    const int KT   = K / 32;

    float acc[2][4][4] = {};

    auto stage_load = [&](int s, int kt) {
        if (kt < KT) {
            int k0 = kt * 32;
            __nv_bfloat16* sAh = sm + s * STG;
            __nv_bfloat16* sAl = sAh + A_SZ;
            __nv_bfloat16* sBh = sAl + A_SZ;
            __nv_bfloat16* sBl = sBh + B_SZ;
            #pragma unroll
            for (int i = 0; i < 2; i++) {
                int id = tid + i * 256;
                int row = id >> 2, c = id & 3;
                long gofs = (long)(row0 + row) * K + k0 + c * 8;
                cp16(sAh + row * BKP + c * 8, Ah + gofs);
                cp16(sAl + row * BKP + c * 8, Al + gofs);
            }
            {
                int n = tid >> 2, c = tid & 3;
                long gofs = (long)(col0 + n) * K + k0 + c * 8;
                cp16(sBh + n * BKP + c * 8, Bth + gofs);
                cp16(sBl + n * BKP + c * 8, Btl + gofs);
            }
        }
        asm volatile("cp.async.commit_group;\n" ::: "memory");
    };

    auto compute = [&](int s) {
        const __nv_bfloat16* sAh = sm + s * STG;
        const __nv_bfloat16* sAl = sAh + A_SZ;
        const __nv_bfloat16* sBh = sAl + A_SZ;
        const __nv_bfloat16* sBl = sBh + B_SZ;
        #pragma unroll
        for (int ks = 0; ks < 32; ks += 16) {
            uint32_t ah[2][4], al[2][4], bh[4][2], bl[4][2];
            #pragma unroll
            for (int f = 0; f < 2; f++) {
                int r = wm * 32 + f * 16 + tr;
                int kk = ks + tc * 2;
                ah[f][0] = *(const uint32_t*)&sAh[r * BKP + kk];
                ah[f][1] = *(const uint32_t*)&sAh[(r + 8) * BKP + kk];
                ah[f][2] = *(const uint32_t*)&sAh[r * BKP + kk + 8];
                ah[f][3] = *(const uint32_t*)&sAh[(r + 8) * BKP + kk + 8];
                al[f][0] = *(const uint32_t*)&sAl[r * BKP + kk];
                al[f][1] = *(const uint32_t*)&sAl[(r + 8) * BKP + kk];
                al[f][2] = *(const uint32_t*)&sAl[r * BKP + kk + 8];
                al[f][3] = *(const uint32_t*)&sAl[(r + 8) * BKP + kk + 8];
            }
            #pragma unroll
            for (int g = 0; g < 4; g++) {
                int n = wn * 32 + g * 8 + tr;
                int kk = ks + tc * 2;
                bh[g][0] = *(const uint32_t*)&sBh[n * BKP + kk];
                bh[g][1] = *(const uint32_t*)&sBh[n * BKP + kk + 8];
                bl[g][0] = *(const uint32_t*)&sBl[n * BKP + kk];
                bl[g][1] = *(const uint32_t*)&sBl[n * BKP + kk + 8];
            }
            #pragma unroll
            for (int f = 0; f < 2; f++)
                #pragma unroll
                for (int g = 0; g < 4; g++) {
                    mma16816(acc[f][g], ah[f], bh[g]);
                    mma16816(acc[f][g], ah[f], bl[g]);
                    mma16816(acc[f][g], al[f], bh[g]);
                }
        }
    };

    stage_load(0, 0);
    stage_load(1, 1);
    for (int kt = 0; kt < KT; kt++) {
        asm volatile("cp.async.wait_group 1;\n" ::: "memory");
        __syncthreads();
        stage_load((kt + 2) % NSTAGE, kt + 2);
        compute(kt % NSTAGE);
    }

    // ---- store C (fp16) ----
    #pragma unroll
    for (int f = 0; f < 2; f++) {
        int r = row0 + wm * 32 + f * 16 + tr;
        #pragma unroll
        for (int g = 0; g < 4; g++) {
            int c = col0 + wn * 32 + g * 8 + tc * 2;
            if (r < M)
                *(__half2*)&C[(long)r * N + c] = __floats2half2_rn(acc[f][g][0], acc[f][g][1]);
            if (r + 8 < M)
                *(__half2*)&C[(long)(r + 8) * N + c] = __floats2half2_rn(acc[f][g][2], acc[f][g][3]);
        }
    }

    // ---- fused alpha epilogue (reads fp32 accumulators: full precision) ----
    float asv[8], adv[8];
    #pragma unroll
    for (int g = 0; g < 4; g++) {
        int colg = col0 + wn * 32 + g * 8 + tc * 2;
        asv[g * 2] = __ldg(&a_s[colg]); asv[g * 2 + 1] = __ldg(&a_s[colg + 1]);
        adv[g * 2] = __ldg(&a_d[colg]); adv[g * 2 + 1] = __ldg(&a_d[colg + 1]);
    }
    const int hlo = (col0 + wn * 32) / Ch;
    const bool two_heads = (Ch == 16);
    #pragma unroll
    for (int f = 0; f < 2; f++) {
        #pragma unroll
        for (int half = 0; half < 2; half++) {
            int row = row0 + wm * 32 + f * 16 + tr + half * 8;
            float psg[4], pdg[4];
            #pragma unroll
            for (int g = 0; g < 4; g++) {
                float a0 = acc[f][g][half * 2], a1 = acc[f][g][half * 2 + 1];
                psg[g] = a0 * asv[g * 2] + a1 * asv[g * 2 + 1];
                pdg[g] = a0 * adv[g * 2] + a1 * adv[g * 2 + 1];
            }
            float s0 = psg[0] + psg[1], s1 = psg[2] + psg[3];
            float d0 = pdg[0] + pdg[1], d1 = pdg[2] + pdg[3];
            #pragma unroll
            for (int o = 1; o <= 2; o <<= 1) {
                s0 += __shfl_xor_sync(0xffffffffu, s0, o);
                s1 += __shfl_xor_sync(0xffffffffu, s1, o);
                d0 += __shfl_xor_sync(0xffffffffu, d0, o);
                d1 += __shfl_xor_sync(0xffffffffu, d1, o);
            }
            if (tc == 0 && row < M) {
                if (two_heads) {
                    atomicAdd(&alpha_s_out[row * 4 + hlo], s0);
                    atomicAdd(&alpha_s_out[row * 4 + hlo + 1], s1);
                    atomicAdd(&alpha_d_out[row * 4 + hlo], d0);
                    atomicAdd(&alpha_d_out[row * 4 + hlo + 1], d1);
                } else {
                    atomicAdd(&alpha_s_out[row * 4 + hlo], s0 + s1);
                    atomicAdd(&alpha_d_out[row * 4 + hlo], d0 + d1);
                }
            }
        }
    }
}

// ========== fused softmax+aggregate kernels (single pass, no max) ==========

// Layer 1: F=256, C=64 -> elu(out+bias) -> split bf16 planes.
__global__ void gat_agg_l1(const float* __restrict__ bias) {
    int dstN = (blockIdx.x * blockDim.x + threadIdx.x) >> 5;
    int lane = threadIdx.x & 31;
    if (dstN >= NNODE) return;
    int r0 = g_rowoff[dstN], r1 = g_rowoff[dstN + 1];
    const float4* a_s = g_alpha_sA;
    float4 ad = g_alpha_dA[dstN];

    const int myh = lane & 3;
    const int hd0 = lane >> 4;
    const int hd1 = 2 + (lane >> 4);
    float4 acc0 = make_float4(0, 0, 0, 0), acc1 = make_float4(0, 0, 0, 0);
    float den0 = 0.f, den1 = 0.f;

    int e = r0;
    for (; e + 1 < r1; e += 2) {
        int sA, sB; float xA0, xA1, xB0, xB1;
        edge_ex2(a_s, e,     ad, myh, hd0, hd1, xA0, xA1, sA);
        edge_ex2(a_s, e + 1, ad, myh, hd0, hd1, xB0, xB1, sB);
        const __half* hA = g_h + (long)sA * 256;
        const __half* hB = g_h + (long)sB * 256;
        float4 vA0 = load4h(hA + lane * 4), vA1 = load4h(hA + 128 + lane * 4);
        float4 vB0 = load4h(hB + lane * 4), vB1 = load4h(hB + 128 + lane * 4);
        acc0.x += vA0.x * xA0 + vB0.x * xB0;  acc0.y += vA0.y * xA0 + vB0.y * xB0;
        acc0.z += vA0.z * xA0 + vB0.z * xB0;  acc0.w += vA0.w * xA0 + vB0.w * xB0;
        acc1.x += vA1.x * xA1 + vB1.x * xB1;  acc1.y += vA1.y * xA1 + vB1.y * xB1;
        acc1.z += vA1.z * xA1 + vB1.z * xB1;  acc1.w += vA1.w * xA1 + vB1.w * xB1;
        den0 += xA0 + xB0;  den1 += xA1 + xB1;
    }
    if (e < r1) {
        int s; float x0, x1;
        edge_ex2(a_s, e, ad, myh, hd0, hd1, x0, x1, s);
        const __half* hp = g_h + (long)s * 256;
        float4 v0 = load4h(hp + lane * 4), v1 = load4h(hp + 128 + lane * 4);
        acc0.x += v0.x * x0; acc0.y += v0.y * x0; acc0.z += v0.z * x0; acc0.w += v0.w * x0;
        acc1.x += v1.x * x1; acc1.y += v1.y * x1; acc1.z += v1.z * x1; acc1.w += v1.w * x1;
        den0 += x0; den1 += x1;
    }

    float iv0 = 1.f / (den0 + 1e-16f), iv1 = 1.f / (den1 + 1e-16f);
    #pragma unroll
    for (int c = 0; c < 2; c++) {
        int f = lane * 4 + c * 128;
        float iv = c == 0 ? iv0 : iv1;
        float4 r = c == 0 ? acc0 : acc1;
        r.x = r.x * iv + bias[f];     r.y = r.y * iv + bias[f + 1];
        r.z = r.z * iv + bias[f + 2]; r.w = r.w * iv + bias[f + 3];
        r.x = r.x > 0.f ? r.x : expm1f(r.x);
        r.y = r.y > 0.f ? r.y : expm1f(r.y);
        r.z = r.z > 0.f ? r.z : expm1f(r.z);
        r.w = r.w > 0.f ? r.w : expm1f(r.w);
        __nv_bfloat16 h0, h1, h2, h3, l0, l1, l2, l3;
        cvt_split(r.x, h0, l0); cvt_split(r.y, h1, l1);
        cvt_split(r.z, h2, l2); cvt_split(r.w, h3, l3);
        long o = (long)dstN * 256 + f;
        *(__nv_bfloat162*)&g_pAh[o]     = __nv_bfloat162(h0, h1);
        *(__nv_bfloat162*)&g_pAh[o + 2] = __nv_bfloat162(h2, h3);
        *(__nv_bfloat162*)&g_pAl[o]     = __nv_bfloat162(l0, l1);
        *(__nv_bfloat162*)&g_pAl[o + 2] = __nv_bfloat162(l2, l3);
    }
    if (lane == 0) {
        g_alpha_sB[dstN] = make_float4(0, 0, 0, 0);
        g_alpha_dB[dstN] = make_float4(0, 0, 0, 0);
    }
}

// Layer 2: F=64, C=16 -> elu(out+bias) -> split bf16 planes.
__global__ void gat_agg_l2(const float* __restrict__ bias) {
    int dstN = (blockIdx.x * blockDim.x + threadIdx.x) >> 5;
    int lane = threadIdx.x & 31;
    if (dstN >= NNODE) return;
    int r0 = g_rowoff[dstN], r1 = g_rowoff[dstN + 1];
    const float4* a_s = g_alpha_sB;
    float4 ad = g_alpha_dB[dstN];

    const int myh = lane & 3;
    const int f = lane * 2;
    const int hd = lane >> 3;
    float a0 = 0.f, a1 = 0.f, den = 0.f;

    int e = r0;
    for (; e + 1 < r1; e += 2) {
        int sA, sB;
        float xA = edge_ex(a_s, e,     ad, myh, hd, sA);
        float xB = edge_ex(a_s, e + 1, ad, myh, hd, sB);
        float2 hA = __half22float2(*(const __half2*)(g_h + (long)sA * 64 + f));
        float2 hB = __half22float2(*(const __half2*)(g_h + (long)sB * 64 + f));
        a0 += hA.x * xA + hB.x * xB;
        a1 += hA.y * xA + hB.y * xB;
        den += xA + xB;
    }
    if (e < r1) {
        int s;
        float x = edge_ex(a_s, e, ad, myh, hd, s);
        float2 hv = __half22float2(*(const __half2*)(g_h + (long)s * 64 + f));
        a0 += hv.x * x; a1 += hv.y * x; den += x;
    }

    float iv = 1.f / (den + 1e-16f);
    a0 = a0 * iv + bias[f];
    a1 = a1 * iv + bias[f + 1];
    a0 = a0 > 0.f ? a0 : expm1f(a0);
    a1 = a1 > 0.f ? a1 : expm1f(a1);
    __nv_bfloat16 h0, h1, l0, l1;
    cvt_split(a0, h0, l0); cvt_split(a1, h1, l1);
    *(__nv_bfloat162*)&g_pAh[(long)dstN * 64 + f] = __nv_bfloat162(h0, h1);
    *(__nv_bfloat162*)&g_pAl[(long)dstN * 64 + f] = __nv_bfloat162(l0, l1);
    if (lane == 0) {
        g_alpha_sA[dstN] = make_float4(0, 0, 0, 0);
        g_alpha_dA[dstN] = make_float4(0, 0, 0, 0);
    }
}

// Layer 3: F=128, C=32, fused head-mean + b3 -> g_z.
__global__ void gat_agg_l3(const float* __restrict__ b3) {
    int dstN = (blockIdx.x * blockDim.x + threadIdx.x) >> 5;
    int lane = threadIdx.x & 31;
    if (dstN >= NNODE) return;
    int r0 = g_rowoff[dstN], r1 = g_rowoff[dstN + 1];
    const float4* a_s = g_alpha_sA;
    float4 ad = g_alpha_dA[dstN];

    const int myh = lane & 3;
    const int hd = lane >> 3;
    float4 acc = make_float4(0, 0, 0, 0);
    float den = 0.f;

    int e = r0;
    for (; e + 1 < r1; e += 2) {
        int sA, sB;
        float xA = edge_ex(a_s, e,     ad, myh, hd, sA);
        float xB = edge_ex(a_s, e + 1, ad, myh, hd, sB);
        float4 vA = load4h(g_h + (long)sA * 128 + lane * 4);
        float4 vB = load4h(g_h + (long)sB * 128 + lane * 4);
        acc.x += vA.x * xA + vB.x * xB;  acc.y += vA.y * xA + vB.y * xB;
        acc.z += vA.z * xA + vB.z * xB;  acc.w += vA.w * xA + vB.w * xB;
        den += xA + xB;
    }
    if (e < r1) {
        int s;
        float x = edge_ex(a_s, e, ad, myh, hd, s);
        float4 v = load4h(g_h + (long)s * 128 + lane * 4);
        acc.x += v.x * x; acc.y += v.y * x; acc.z += v.z * x; acc.w += v.w * x;
        den += x;
    }

    float iv = 1.f / (den + 1e-16f);
    acc.x *= iv; acc.y *= iv; acc.z *= iv; acc.w *= iv;
    #pragma unroll
    for (int o = 8; o <= 16; o <<= 1) {
        acc.x += __shfl_xor_sync(0xffffffffu, acc.x, o);
        acc.y += __shfl_xor_sync(0xffffffffu, acc.y, o);
        acc.z += __shfl_xor_sync(0xffffffffu, acc.z, o);
        acc.w += __shfl_xor_sync(0xffffffffu, acc.w, o);
    }
    if (lane < 8) {
        int c = lane * 4;
        float4 z = make_float4(0.25f * acc.x + b3[c],     0.25f * acc.y + b3[c + 1],
                               0.25f * acc.z + b3[c + 2], 0.25f * acc.w + b3[c + 3]);
        *(float4*)&g_z[(long)dstN * 32 + c] = z;
    }
}

// ---------------- logits: 8 lanes per candidate edge (4 edges/warp) ----------
__global__ void dot_kernel(const void* __restrict__ eli, float* __restrict__ out) {
    int gw = (blockIdx.x * blockDim.x + threadIdx.x) >> 5;
    int lane = threadIdx.x & 31;
    int sub = lane >> 3, sl = lane & 7;
    int w = gw * 4 + sub;
    if (w >= ECAND) return;   // ECAND % 4 == 0: whole warps exit together
    int use64 = g_idx64_eli;
    int s = load_idx(eli, use64, w);
    int d = load_idx(eli, use64, (long long)ECAND + w);
    float4 a = ((const float4*)(g_z + (long)s * 32))[sl];
    float4 b = ((const float4*)(g_z + (long)d * 32))[sl];
    float p = a.x * b.x + a.y * b.y + a.z * b.z + a.w * b.w;
    #pragma unroll
    for (int o = 1; o <= 4; o <<= 1) p += __shfl_xor_sync(0xffffffffu, p, o);
    if (sl == 0) out[w] = p;
}

// ---------------- host launch ----------------
extern "C" void kernel_launch(void* const* d_in, const int* in_sizes, int n_in,
                              void* d_out, int out_size) {
    const float* x   = (const float*)d_in[0];
    const void*  ei  = d_in[1];
    const void*  eli = d_in[2];
    const float* W1  = (const float*)d_in[3];
    const float* a1s = (const float*)d_in[4];
    const float* a1d = (const float*)d_in[5];
    const float* b1  = (const float*)d_in[6];
    const float* W2  = (const float*)d_in[7];
    const float* a2s = (const float*)d_in[8];
    const float* a2d = (const float*)d_in[9];
    const float* b2  = (const float*)d_in[10];
    const float* W3  = (const float*)d_in[11];
    const float* a3s = (const float*)d_in[12];
    const float* a3d = (const float*)d_in[13];
    const float* b3  = (const float*)d_in[14];
    float* out = (float*)d_out;

    __half* p_h;
    cudaGetSymbolAddress((void**)&p_h, g_h);
    __nv_bfloat16 *p_Ah, *p_Al, *p_Bh, *p_Bl;
    cudaGetSymbolAddress((void**)&p_Ah, g_pAh);
    cudaGetSymbolAddress((void**)&p_Al, g_pAl);
    cudaGetSymbolAddress((void**)&p_Bh, g_pBh);
    cudaGetSymbolAddress((void**)&p_Bl, g_pBl);
    float *p_asA, *p_adA, *p_asB, *p_adB;
    cudaGetSymbolAddress((void**)&p_asA, g_alpha_sA);
    cudaGetSymbolAddress((void**)&p_adA, g_alpha_dA);
    cudaGetSymbolAddress((void**)&p_asB, g_alpha_sB);
    cudaGetSymbolAddress((void**)&p_adB, g_alpha_dB);

    static cudaStream_t sB = nullptr;
    static cudaEvent_t evFork = nullptr, evInit = nullptr, evJoin = nullptr;
    static bool attr_done = false;
    if (!attr_done) {
        cudaFuncSetAttribute(gemm_tc, cudaFuncAttributeMaxDynamicSharedMemorySize, GEMM_SMEM);
        cudaStreamCreateWithFlags(&sB, cudaStreamNonBlocking);
        cudaEventCreateWithFlags(&evFork, cudaEventDisableTiming);
        cudaEventCreateWithFlags(&evInit, cudaEventDisableTiming);
        cudaEventCreateWithFlags(&evJoin, cudaEventDisableTiming);
        attr_done = true;
    }

    const int TB = 256;
    const int nodeWarpBlocks = (NNODE * 32 + TB - 1) / TB;
    const int MB = (NNODE + 127) / 128;

    // ---- fork at t=0: side stream joins capture via event on stream 0 ----
    cudaEventRecord(evFork, 0);
    cudaStreamWaitEvent(sB, evFork, 0);

    // ---- side stream: init (alphaA zero + dtype flags + cnt) then CSR ----
    init_detect<<<(NNODE + TB - 1) / TB, TB, 0, sB>>>((const int*)ei, (const int*)eli);
    cudaEventRecord(evInit, sB);
    hist_edges<<<(NEDGE + TB - 1) / TB, TB, 0, sB>>>(ei);
    csr_s1<<<NBLK, 1024, 0, sB>>>();
    csr_s2<<<1, 64, 0, sB>>>();
    csr_s3<<<NBLK, 1024, 0, sB>>>();
    scatter_edges<<<(NEDGE + TB - 1) / TB, TB, 0, sB>>>(ei);
    cudaEventRecord(evJoin, sB);

    // ---- main stream: split starts at t=0 (depends only on inputs) ----
    split_all<<<(NX4 + 122880 + TB - 1) / TB, TB>>>(x, W1, W2, W3);
    cudaStreamWaitEvent(0, evInit, 0);   // gemm1 accumulates into alphaA (zeroed by init)
    gemm_tc<<<dim3(4, MB), 256, GEMM_SMEM>>>(p_Ah, p_Al, p_Bh, p_Bl, p_h,
                                             a1s, a1d, p_asA, p_adA, NNODE, 256, 384, 64);

    // ---- join: aggregates need the CSR ----
    cudaStreamWaitEvent(0, evJoin, 0);
    gat_agg_l1<<<nodeWarpBlocks, TB>>>(b1);

    // ---- Layer 2 ----
    gemm_tc<<<dim3(1, MB), 256, GEMM_SMEM>>>(p_Ah, p_Al, p_Bh + 98304, p_Bl + 98304, p_h,
                                             a2s, a2d, p_asB, p_adB, NNODE, 64, 256, 16);
    gat_agg_l2<<<nodeWarpBlocks, TB>>>(b2);

    // ---- Layer 3 ----
    gemm_tc<<<dim3(2, MB), 256, GEMM_SMEM>>>(p_Ah, p_Al, p_Bh + 114688, p_Bl + 114688, p_h,
                                             a3s, a3d, p_asA, p_adA, NNODE, 128, 64, 32);
    gat_agg_l3<<<nodeWarpBlocks, TB>>>(b3);

    // ---- Candidate-edge logits (4 edges per warp) ----
    dot_kernel<<<(ECAND / 4 * 32 + TB - 1) / TB, TB>>>(eli, out);
}

// round 17
// speedup vs baseline: 1.3247x; 1.2079x over previous
#include <cuda_runtime.h>
#include <cuda_bf16.h>
#include <cuda_fp16.h>
#include <math.h>
#include <stdint.h>

#define NNODE   50000
#define NEDGE   800000
#define ET      850000      // NEDGE + NNODE self loops
#define ECAND   200000
#define MPAD    50048       // ceil(NNODE/128)*128
#define KMAX    384
#define NBLK    49          // ceil(NNODE/1024)

// ---------------- scratch (device globals; no allocation) ----------------
__device__ __align__(16) __half g_pA[MPAD * KMAX];   // A plane (fp16)
// packed W plane [N][K]: L1 @0 (384*256), L2 @98304 (256*64), L3 @114688 (64*128)
__device__ __align__(16) __half g_pB[122880];
__device__ __align__(16) __half g_h[NNODE * 256];    // GEMM output (fp16)
// ping-pong alpha buffers
__device__ float4 g_alpha_sA[NNODE];
__device__ float4 g_alpha_dA[NNODE];
__device__ float4 g_alpha_sB[NNODE];
__device__ float4 g_alpha_dB[NNODE];
__device__ int    g_esrc[ET];
__device__ int    g_rowoff[NNODE + 1];
__device__ int    g_cnt[NNODE];
__device__ int    g_cursor[NNODE];
__device__ int    g_bsum[64];
__device__ int    g_boff[64];
__device__ __align__(16) float g_z[NNODE * 32];
__device__ int    g_idx64_ei;
__device__ int    g_idx64_eli;

// ---------------- helpers ----------------
__device__ __forceinline__ float lrelu(float v) { return v > 0.f ? v : 0.2f * v; }

__device__ __forceinline__ float sel4(float4 v, int h) {
    return h < 2 ? (h == 0 ? v.x : v.y) : (h == 2 ? v.z : v.w);
}

__device__ __forceinline__ int load_idx(const void* p, int use64, long long pos) {
    return use64 ? (int)((const long long*)p)[pos] : ((const int*)p)[pos];
}

__device__ __forceinline__ void cp16(const void* s, const void* g) {
    uint32_t sa = (uint32_t)__cvta_generic_to_shared(s);
    asm volatile("cp.async.cg.shared.global [%0], [%1], 16;\n" :: "r"(sa), "l"(g));
}

// load 4 consecutive halves -> float4 (8-byte vectorized)
__device__ __forceinline__ float4 load4h(const __half* p) {
    uint2 u = *(const uint2*)p;
    float2 f01 = __half22float2(*(__half2*)&u.x);
    float2 f23 = __half22float2(*(__half2*)&u.y);
    return make_float4(f01.x, f01.y, f23.x, f23.y);
}

// per-edge: ex for one head, computed warp-wide (lane L evals head L&3),
// fetched per-lane via shfl. No max subtraction (softmax is shift-invariant;
// |e| <~ 15 here so exp stays far from fp32 limits).
__device__ __forceinline__ float edge_ex(const float4* __restrict__ a_s,
                                         int e, float4 ad, int myh,
                                         int want, int& src) {
    src = g_esrc[e];
    float4 s = a_s[src];
    float eh = sel4(make_float4(lrelu(s.x + ad.x), lrelu(s.y + ad.y),
                                lrelu(s.z + ad.z), lrelu(s.w + ad.w)), myh);
    float ex = __expf(eh);
    return __shfl_sync(0xffffffffu, ex, want);
}

__device__ __forceinline__ void edge_ex2(const float4* __restrict__ a_s,
                                         int e, float4 ad, int myh,
                                         int w0, int w1, float& ex0, float& ex1, int& src) {
    src = g_esrc[e];
    float4 s = a_s[src];
    float eh = sel4(make_float4(lrelu(s.x + ad.x), lrelu(s.y + ad.y),
                                lrelu(s.z + ad.z), lrelu(s.w + ad.w)), myh);
    float ex = __expf(eh);
    ex0 = __shfl_sync(0xffffffffu, ex, w0);
    ex1 = __shfl_sync(0xffffffffu, ex, w1);
}

// ---------------- init: dtype detect + cnt=1 + alphaA zero ----------------
__global__ void init_detect(const int* __restrict__ ei, const int* __restrict__ eli) {
    int i = blockIdx.x * blockDim.x + threadIdx.x;
    if (i < NNODE) {
        g_cnt[i] = 1;
        g_alpha_sA[i] = make_float4(0, 0, 0, 0);
        g_alpha_dA[i] = make_float4(0, 0, 0, 0);
    }
    if (i == 0) {
        int ok = 1;
        #pragma unroll
        for (int j = 1; j < 64; j += 2) if (ei[j] != 0) { ok = 0; break; }
        g_idx64_ei = ok;
        ok = 1;
        #pragma unroll
        for (int j = 1; j < 64; j += 2) if (eli[j] != 0) { ok = 0; break; }
        g_idx64_eli = ok;
    }
}

// ================= operand conversion (x + all weights, one launch) =========
#define NX4 (NNODE * 384 / 4)
__global__ void split_all(const float* __restrict__ x, const float* __restrict__ W1,
                          const float* __restrict__ W2, const float* __restrict__ W3) {
    int t = blockIdx.x * blockDim.x + threadIdx.x;
    if (t < NX4) {
        long i = (long)t * 4;
        float4 v = *(const float4*)(x + i);
        *(__half2*)&g_pA[i]     = __floats2half2_rn(v.x, v.y);
        *(__half2*)&g_pA[i + 2] = __floats2half2_rn(v.z, v.w);
        return;
    }
    int i = t - NX4;
    const float* W; int K, N, off, li;
    if (i < 98304)       { W = W1; K = 384; N = 256; off = 0;      li = i; }
    else if (i < 114688) { W = W2; K = 256; N = 64;  off = 98304;  li = i - 98304; }
    else if (i < 122880) { W = W3; K = 64;  N = 128; off = 114688; li = i - 114688; }
    else return;
    int k = li / N, n = li % N;
    g_pB[off + n * K + k] = __float2half_rn(W[li]);
}

// ================= CSR build (parallel scan) =================
__global__ void hist_edges(const void* __restrict__ ei) {
    int e = blockIdx.x * blockDim.x + threadIdx.x;
    if (e >= NEDGE) return;
    int dst = load_idx(ei, g_idx64_ei, (long long)NEDGE + e);
    atomicAdd(&g_cnt[dst], 1);
}

__global__ void csr_s1() {
    __shared__ int ws[32];
    int i = blockIdx.x * 1024 + threadIdx.x;
    int lane = threadIdx.x & 31, wid = threadIdx.x >> 5;
    int v = (i < NNODE) ? g_cnt[i] : 0;
    #pragma unroll
    for (int o = 16; o; o >>= 1) v += __shfl_xor_sync(0xffffffffu, v, o);
    if (lane == 0) ws[wid] = v;
    __syncthreads();
    if (threadIdx.x < 32) {
        int s = ws[threadIdx.x];
        #pragma unroll
        for (int o = 16; o; o >>= 1) s += __shfl_xor_sync(0xffffffffu, s, o);
        if (threadIdx.x == 0) g_bsum[blockIdx.x] = s;
    }
}

__global__ void csr_s2() {
    __shared__ int w0tot;
    int t = threadIdx.x;
    int lane = t & 31, w = t >> 5;
    int v = (t < NBLK) ? g_bsum[t] : 0;
    int x = v;
    #pragma unroll
    for (int o = 1; o < 32; o <<= 1) {
        int y = __shfl_up_sync(0xffffffffu, x, o);
        if (lane >= o) x += y;
    }
    if (t == 31) w0tot = x;
    __syncthreads();
    if (w == 1) x += w0tot;
    if (t < NBLK) g_boff[t] = x - v;
}

__global__ void csr_s3() {
    __shared__ int ws[32];
    int i = blockIdx.x * 1024 + threadIdx.x;
    int lane = threadIdx.x & 31, wid = threadIdx.x >> 5;
    int v = (i < NNODE) ? g_cnt[i] : 0;
    int x = v;
    #pragma unroll
    for (int o = 1; o < 32; o <<= 1) {
        int y = __shfl_up_sync(0xffffffffu, x, o);
        if (lane >= o) x += y;
    }
    if (lane == 31) ws[wid] = x;
    __syncthreads();
    if (wid == 0) {
        int s = ws[lane];
        #pragma unroll
        for (int o = 1; o < 32; o <<= 1) {
            int y = __shfl_up_sync(0xffffffffu, s, o);
            if (lane >= o) s += y;
        }
        ws[lane] = s;
    }
    __syncthreads();
    int ex = x - v + (wid ? ws[wid - 1] : 0) + g_boff[blockIdx.x];
    if (i < NNODE) {
        g_rowoff[i] = ex;
        g_cursor[i] = ex + 1;
        g_esrc[ex] = i;
        if (i == NNODE - 1) g_rowoff[NNODE] = ex + v;
    }
}

__global__ void scatter_edges(const void* __restrict__ ei) {
    int e = blockIdx.x * blockDim.x + threadIdx.x;
    if (e >= NEDGE) return;
    int use64 = g_idx64_ei;
    int src = load_idx(ei, use64, e);
    int dst = load_idx(ei, use64, (long long)NEDGE + e);
    int pos = atomicAdd(&g_cursor[dst], 1);
    g_esrc[pos] = src;
}

// ======= fp16 mma.sync GEMM, 3-stage cp.async + fused alpha =========
#define BKP 40
#define A_SZ (128 * BKP)
#define B_SZ (64 * BKP)
#define STG  (A_SZ + B_SZ)
#define NSTAGE 3
#define GEMM_SMEM (NSTAGE * STG * 2)   // 46080 bytes

__device__ __forceinline__ void mma16816(float* c, const uint32_t* a, const uint32_t* b) {
    asm volatile(
        "mma.sync.aligned.m16n8k16.row.col.f32.f16.f16.f32 "
        "{%0,%1,%2,%3}, {%4,%5,%6,%7}, {%8,%9}, {%0,%1,%2,%3};\n"
        : "+f"(c[0]), "+f"(c[1]), "+f"(c[2]), "+f"(c[3])
        : "r"(a[0]), "r"(a[1]), "r"(a[2]), "r"(a[3]), "r"(b[0]), "r"(b[1]));
}

__global__ __launch_bounds__(256) void gemm_tc(const __half* __restrict__ A,
                                               const __half* __restrict__ Bt,
                                               __half* __restrict__ C,
                                               const float* __restrict__ a_s,
                                               const float* __restrict__ a_d,
                                               float* __restrict__ alpha_s_out,
                                               float* __restrict__ alpha_d_out,
                                               int M, int N, int K, int Ch) {
    extern __shared__ __half sm[];
    const int tid  = threadIdx.x;
    const int lane = tid & 31;
    const int warp = tid >> 5;
    const int wm   = warp & 3;
    const int wn   = warp >> 2;
    const int tr   = lane >> 2;
    const int tc   = lane & 3;
    const int row0 = blockIdx.y * 128;
    const int col0 = blockIdx.x * 64;
    const int KT   = K / 32;

    float acc[2][4][4] = {};

    auto stage_load = [&](int s, int kt) {
        if (kt < KT) {
            int k0 = kt * 32;
            __half* sA = sm + s * STG;
            __half* sB = sA + A_SZ;
            #pragma unroll
            for (int i = 0; i < 2; i++) {
                int id = tid + i * 256;           // 0..511
                int row = id >> 2, c = id & 3;
                long gofs = (long)(row0 + row) * K + k0 + c * 8;
                cp16(sA + row * BKP + c * 8, A + gofs);
            }
            {
                int n = tid >> 2, c = tid & 3;    // 256 chunks
                long gofs = (long)(col0 + n) * K + k0 + c * 8;
                cp16(sB + n * BKP + c * 8, Bt + gofs);
            }
        }
        asm volatile("cp.async.commit_group;\n" ::: "memory");
    };

    auto compute = [&](int s) {
        const __half* sA = sm + s * STG;
        const __half* sB = sA + A_SZ;
        #pragma unroll
        for (int ks = 0; ks < 32; ks += 16) {
            uint32_t a[2][4], b[4][2];
            #pragma unroll
            for (int f = 0; f < 2; f++) {
                int r = wm * 32 + f * 16 + tr;
                int kk = ks + tc * 2;
                a[f][0] = *(const uint32_t*)&sA[r * BKP + kk];
                a[f][1] = *(const uint32_t*)&sA[(r + 8) * BKP + kk];
                a[f][2] = *(const uint32_t*)&sA[r * BKP + kk + 8];
                a[f][3] = *(const uint32_t*)&sA[(r + 8) * BKP + kk + 8];
            }
            #pragma unroll
            for (int g = 0; g < 4; g++) {
                int n = wn * 32 + g * 8 + tr;
                int kk = ks + tc * 2;
                b[g][0] = *(const uint32_t*)&sB[n * BKP + kk];
                b[g][1] = *(const uint32_t*)&sB[n * BKP + kk + 8];
            }
            #pragma unroll
            for (int f = 0; f < 2; f++)
                #pragma unroll
                for (int g = 0; g < 4; g++)
                    mma16816(acc[f][g], a[f], b[g]);
        }
    };

    stage_load(0, 0);
    stage_load(1, 1);
    for (int kt = 0; kt < KT; kt++) {
        asm volatile("cp.async.wait_group 1;\n" ::: "memory");
        __syncthreads();
        stage_load((kt + 2) % NSTAGE, kt + 2);
        compute(kt % NSTAGE);
    }

    // ---- store C (fp16) ----
    #pragma unroll
    for (int f = 0; f < 2; f++) {
        int r = row0 + wm * 32 + f * 16 + tr;
        #pragma unroll
        for (int g = 0; g < 4; g++) {
            int c = col0 + wn * 32 + g * 8 + tc * 2;
            if (r < M)
                *(__half2*)&C[(long)r * N + c] = __floats2half2_rn(acc[f][g][0], acc[f][g][1]);
            if (r + 8 < M)
                *(__half2*)&C[(long)(r + 8) * N + c] = __floats2half2_rn(acc[f][g][2], acc[f][g][3]);
        }
    }

    // ---- fused alpha epilogue (reads fp32 accumulators) ----
    float asv[8], adv[8];
    #pragma unroll
    for (int g = 0; g < 4; g++) {
        int colg = col0 + wn * 32 + g * 8 + tc * 2;
        asv[g * 2] = __ldg(&a_s[colg]); asv[g * 2 + 1] = __ldg(&a_s[colg + 1]);
        adv[g * 2] = __ldg(&a_d[colg]); adv[g * 2 + 1] = __ldg(&a_d[colg + 1]);
    }
    const int hlo = (col0 + wn * 32) / Ch;
    const bool two_heads = (Ch == 16);
    #pragma unroll
    for (int f = 0; f < 2; f++) {
        #pragma unroll
        for (int half = 0; half < 2; half++) {
            int row = row0 + wm * 32 + f * 16 + tr + half * 8;
            float psg[4], pdg[4];
            #pragma unroll
            for (int g = 0; g < 4; g++) {
                float a0 = acc[f][g][half * 2], a1 = acc[f][g][half * 2 + 1];
                psg[g] = a0 * asv[g * 2] + a1 * asv[g * 2 + 1];
                pdg[g] = a0 * adv[g * 2] + a1 * adv[g * 2 + 1];
            }
            float s0 = psg[0] + psg[1], s1 = psg[2] + psg[3];
            float d0 = pdg[0] + pdg[1], d1 = pdg[2] + pdg[3];
            #pragma unroll
            for (int o = 1; o <= 2; o <<= 1) {
                s0 += __shfl_xor_sync(0xffffffffu, s0, o);
                s1 += __shfl_xor_sync(0xffffffffu, s1, o);
                d0 += __shfl_xor_sync(0xffffffffu, d0, o);
                d1 += __shfl_xor_sync(0xffffffffu, d1, o);
            }
            if (tc == 0 && row < M) {
                if (two_heads) {
                    atomicAdd(&alpha_s_out[row * 4 + hlo], s0);
                    atomicAdd(&alpha_s_out[row * 4 + hlo + 1], s1);
                    atomicAdd(&alpha_d_out[row * 4 + hlo], d0);
                    atomicAdd(&alpha_d_out[row * 4 + hlo + 1], d1);
                } else {
                    atomicAdd(&alpha_s_out[row * 4 + hlo], s0 + s1);
                    atomicAdd(&alpha_d_out[row * 4 + hlo], d0 + d1);
                }
            }
        }
    }
}

// ========== fused softmax+aggregate kernels (single pass, no max) ==========

// Layer 1: F=256, C=64 -> elu(out+bias) -> fp16 A plane.
__global__ void gat_agg_l1(const float* __restrict__ bias) {
    int dstN = (blockIdx.x * blockDim.x + threadIdx.x) >> 5;
    int lane = threadIdx.x & 31;
    if (dstN >= NNODE) return;
    int r0 = g_rowoff[dstN], r1 = g_rowoff[dstN + 1];
    const float4* a_s = g_alpha_sA;
    float4 ad = g_alpha_dA[dstN];

    const int myh = lane & 3;
    const int hd0 = lane >> 4;
    const int hd1 = 2 + (lane >> 4);
    float4 acc0 = make_float4(0, 0, 0, 0), acc1 = make_float4(0, 0, 0, 0);
    float den0 = 0.f, den1 = 0.f;

    int e = r0;
    for (; e + 1 < r1; e += 2) {
        int sA, sB; float xA0, xA1, xB0, xB1;
        edge_ex2(a_s, e,     ad, myh, hd0, hd1, xA0, xA1, sA);
        edge_ex2(a_s, e + 1, ad, myh, hd0, hd1, xB0, xB1, sB);
        const __half* hA = g_h + (long)sA * 256;
        const __half* hB = g_h + (long)sB * 256;
        float4 vA0 = load4h(hA + lane * 4), vA1 = load4h(hA + 128 + lane * 4);
        float4 vB0 = load4h(hB + lane * 4), vB1 = load4h(hB + 128 + lane * 4);
        acc0.x += vA0.x * xA0 + vB0.x * xB0;  acc0.y += vA0.y * xA0 + vB0.y * xB0;
        acc0.z += vA0.z * xA0 + vB0.z * xB0;  acc0.w += vA0.w * xA0 + vB0.w * xB0;
        acc1.x += vA1.x * xA1 + vB1.x * xB1;  acc1.y += vA1.y * xA1 + vB1.y * xB1;
        acc1.z += vA1.z * xA1 + vB1.z * xB1;  acc1.w += vA1.w * xA1 + vB1.w * xB1;
        den0 += xA0 + xB0;  den1 += xA1 + xB1;
    }
    if (e < r1) {
        int s; float x0, x1;
        edge_ex2(a_s, e, ad, myh, hd0, hd1, x0, x1, s);
        const __half* hp = g_h + (long)s * 256;
        float4 v0 = load4h(hp + lane * 4), v1 = load4h(hp + 128 + lane * 4);
        acc0.x += v0.x * x0; acc0.y += v0.y * x0; acc0.z += v0.z * x0; acc0.w += v0.w * x0;
        acc1.x += v1.x * x1; acc1.y += v1.y * x1; acc1.z += v1.z * x1; acc1.w += v1.w * x1;
        den0 += x0; den1 += x1;
    }

    float iv0 = 1.f / (den0 + 1e-16f), iv1 = 1.f / (den1 + 1e-16f);
    #pragma unroll
    for (int c = 0; c < 2; c++) {
        int f = lane * 4 + c * 128;
        float iv = c == 0 ? iv0 : iv1;
        float4 r = c == 0 ? acc0 : acc1;
        r.x = r.x * iv + bias[f];     r.y = r.y * iv + bias[f + 1];
        r.z = r.z * iv + bias[f + 2]; r.w = r.w * iv + bias[f + 3];
        r.x = r.x > 0.f ? r.x : expm1f(r.x);
        r.y = r.y > 0.f ? r.y : expm1f(r.y);
        r.z = r.z > 0.f ? r.z : expm1f(r.z);
        r.w = r.w > 0.f ? r.w : expm1f(r.w);
        long o = (long)dstN * 256 + f;
        *(__half2*)&g_pA[o]     = __floats2half2_rn(r.x, r.y);
        *(__half2*)&g_pA[o + 2] = __floats2half2_rn(r.z, r.w);
    }
    if (lane == 0) {
        g_alpha_sB[dstN] = make_float4(0, 0, 0, 0);
        g_alpha_dB[dstN] = make_float4(0, 0, 0, 0);
    }
}

// Layer 2: F=64, C=16 -> elu(out+bias) -> fp16 A plane.
__global__ void gat_agg_l2(const float* __restrict__ bias) {
    int dstN = (blockIdx.x * blockDim.x + threadIdx.x) >> 5;
    int lane = threadIdx.x & 31;
    if (dstN >= NNODE) return;
    int r0 = g_rowoff[dstN], r1 = g_rowoff[dstN + 1];
    const float4* a_s = g_alpha_sB;
    float4 ad = g_alpha_dB[dstN];

    const int myh = lane & 3;
    const int f = lane * 2;
    const int hd = lane >> 3;
    float a0 = 0.f, a1 = 0.f, den = 0.f;

    int e = r0;
    for (; e + 1 < r1; e += 2) {
        int sA, sB;
        float xA = edge_ex(a_s, e,     ad, myh, hd, sA);
        float xB = edge_ex(a_s, e + 1, ad, myh, hd, sB);
        float2 hA = __half22float2(*(const __half2*)(g_h + (long)sA * 64 + f));
        float2 hB = __half22float2(*(const __half2*)(g_h + (long)sB * 64 + f));
        a0 += hA.x * xA + hB.x * xB;
        a1 += hA.y * xA + hB.y * xB;
        den += xA + xB;
    }
    if (e < r1) {
        int s;
        float x = edge_ex(a_s, e, ad, myh, hd, s);
        float2 hv = __half22float2(*(const __half2*)(g_h + (long)s * 64 + f));
        a0 += hv.x * x; a1 += hv.y * x; den += x;
    }

    float iv = 1.f / (den + 1e-16f);
    a0 = a0 * iv + bias[f];
    a1 = a1 * iv + bias[f + 1];
    a0 = a0 > 0.f ? a0 : expm1f(a0);
    a1 = a1 > 0.f ? a1 : expm1f(a1);
    *(__half2*)&g_pA[(long)dstN * 64 + f] = __floats2half2_rn(a0, a1);
    if (lane == 0) {
        g_alpha_sA[dstN] = make_float4(0, 0, 0, 0);
        g_alpha_dA[dstN] = make_float4(0, 0, 0, 0);
    }
}

// Layer 3: F=128, C=32, fused head-mean + b3 -> g_z.
__global__ void gat_agg_l3(const float* __restrict__ b3) {
    int dstN = (blockIdx.x * blockDim.x + threadIdx.x) >> 5;
    int lane = threadIdx.x & 31;
    if (dstN >= NNODE) return;
    int r0 = g_rowoff[dstN], r1 = g_rowoff[dstN + 1];
    const float4* a_s = g_alpha_sA;
    float4 ad = g_alpha_dA[dstN];

    const int myh = lane & 3;
    const int hd = lane >> 3;
    float4 acc = make_float4(0, 0, 0, 0);
    float den = 0.f;

    int e = r0;
    for (; e + 1 < r1; e += 2) {
        int sA, sB;
        float xA = edge_ex(a_s, e,     ad, myh, hd, sA);
        float xB = edge_ex(a_s, e + 1, ad, myh, hd, sB);
        float4 vA = load4h(g_h + (long)sA * 128 + lane * 4);
        float4 vB = load4h(g_h + (long)sB * 128 + lane * 4);
        acc.x += vA.x * xA + vB.x * xB;  acc.y += vA.y * xA + vB.y * xB;
        acc.z += vA.z * xA + vB.z * xB;  acc.w += vA.w * xA + vB.w * xB;
        den += xA + xB;
    }
    if (e < r1) {
        int s;
        float x = edge_ex(a_s, e, ad, myh, hd, s);
        float4 v = load4h(g_h + (long)s * 128 + lane * 4);
        acc.x += v.x * x; acc.y += v.y * x; acc.z += v.z * x; acc.w += v.w * x;
        den += x;
    }

    float iv = 1.f / (den + 1e-16f);
    acc.x *= iv; acc.y *= iv; acc.z *= iv; acc.w *= iv;
    #pragma unroll
    for (int o = 8; o <= 16; o <<= 1) {
        acc.x += __shfl_xor_sync(0xffffffffu, acc.x, o);
        acc.y += __shfl_xor_sync(0xffffffffu, acc.y, o);
        acc.z += __shfl_xor_sync(0xffffffffu, acc.z, o);
        acc.w += __shfl_xor_sync(0xffffffffu, acc.w, o);
    }
    if (lane < 8) {
        int c = lane * 4;
        float4 z = make_float4(0.25f * acc.x + b3[c],     0.25f * acc.y + b3[c + 1],
                               0.25f * acc.z + b3[c + 2], 0.25f * acc.w + b3[c + 3]);
        *(float4*)&g_z[(long)dstN * 32 + c] = z;
    }
}

// ---------------- logits: 8 lanes per candidate edge (4 edges/warp) ----------
__global__ void dot_kernel(const void* __restrict__ eli, float* __restrict__ out) {
    int gw = (blockIdx.x * blockDim.x + threadIdx.x) >> 5;
    int lane = threadIdx.x & 31;
    int sub = lane >> 3, sl = lane & 7;
    int w = gw * 4 + sub;
    if (w >= ECAND) return;   // ECAND % 4 == 0: whole warps exit together
    int use64 = g_idx64_eli;
    int s = load_idx(eli, use64, w);
    int d = load_idx(eli, use64, (long long)ECAND + w);
    float4 a = ((const float4*)(g_z + (long)s * 32))[sl];
    float4 b = ((const float4*)(g_z + (long)d * 32))[sl];
    float p = a.x * b.x + a.y * b.y + a.z * b.z + a.w * b.w;
    #pragma unroll
    for (int o = 1; o <= 4; o <<= 1) p += __shfl_xor_sync(0xffffffffu, p, o);
    if (sl == 0) out[w] = p;
}

// ---------------- host launch ----------------
extern "C" void kernel_launch(void* const* d_in, const int* in_sizes, int n_in,
                              void* d_out, int out_size) {
    const float* x   = (const float*)d_in[0];
    const void*  ei  = d_in[1];
    const void*  eli = d_in[2];
    const float* W1  = (const float*)d_in[3];
    const float* a1s = (const float*)d_in[4];
    const float* a1d = (const float*)d_in[5];
    const float* b1  = (const float*)d_in[6];
    const float* W2  = (const float*)d_in[7];
    const float* a2s = (const float*)d_in[8];
    const float* a2d = (const float*)d_in[9];
    const float* b2  = (const float*)d_in[10];
    const float* W3  = (const float*)d_in[11];
    const float* a3s = (const float*)d_in[12];
    const float* a3d = (const float*)d_in[13];
    const float* b3  = (const float*)d_in[14];
    float* out = (float*)d_out;

    __half *p_h, *p_A, *p_B;
    cudaGetSymbolAddress((void**)&p_h, g_h);
    cudaGetSymbolAddress((void**)&p_A, g_pA);
    cudaGetSymbolAddress((void**)&p_B, g_pB);
    float *p_asA, *p_adA, *p_asB, *p_adB;
    cudaGetSymbolAddress((void**)&p_asA, g_alpha_sA);
    cudaGetSymbolAddress((void**)&p_adA, g_alpha_dA);
    cudaGetSymbolAddress((void**)&p_asB, g_alpha_sB);
    cudaGetSymbolAddress((void**)&p_adB, g_alpha_dB);

    static cudaStream_t sB = nullptr;
    static cudaEvent_t evFork = nullptr, evInit = nullptr, evJoin = nullptr;
    static bool attr_done = false;
    if (!attr_done) {
        cudaFuncSetAttribute(gemm_tc, cudaFuncAttributeMaxDynamicSharedMemorySize, GEMM_SMEM);
        cudaStreamCreateWithFlags(&sB, cudaStreamNonBlocking);
        cudaEventCreateWithFlags(&evFork, cudaEventDisableTiming);
        cudaEventCreateWithFlags(&evInit, cudaEventDisableTiming);
        cudaEventCreateWithFlags(&evJoin, cudaEventDisableTiming);
        attr_done = true;
    }

    const int TB = 256;
    const int nodeWarpBlocks = (NNODE * 32 + TB - 1) / TB;
    const int MB = (NNODE + 127) / 128;

    // ---- fork at t=0: side stream joins capture via event on stream 0 ----
    cudaEventRecord(evFork, 0);
    cudaStreamWaitEvent(sB, evFork, 0);

    // ---- side stream: init (alphaA zero + dtype flags + cnt) then CSR ----
    init_detect<<<(NNODE + TB - 1) / TB, TB, 0, sB>>>((const int*)ei, (const int*)eli);
    cudaEventRecord(evInit, sB);
    hist_edges<<<(NEDGE + TB - 1) / TB, TB, 0, sB>>>(ei);
    csr_s1<<<NBLK, 1024, 0, sB>>>();
    csr_s2<<<1, 64, 0, sB>>>();
    csr_s3<<<NBLK, 1024, 0, sB>>>();
    scatter_edges<<<(NEDGE + TB - 1) / TB, TB, 0, sB>>>(ei);
    cudaEventRecord(evJoin, sB);

    // ---- main stream: convert starts at t=0 (depends only on inputs) ----
    split_all<<<(NX4 + 122880 + TB - 1) / TB, TB>>>(x, W1, W2, W3);
    cudaStreamWaitEvent(0, evInit, 0);   // gemm1 accumulates into alphaA (zeroed by init)
    gemm_tc<<<dim3(4, MB), 256, GEMM_SMEM>>>(p_A, p_B, p_h,
                                             a1s, a1d, p_asA, p_adA, NNODE, 256, 384, 64);

    // ---- join: aggregates need the CSR ----
    cudaStreamWaitEvent(0, evJoin, 0);
    gat_agg_l1<<<nodeWarpBlocks, TB>>>(b1);

    // ---- Layer 2 ----
    gemm_tc<<<dim3(1, MB), 256, GEMM_SMEM>>>(p_A, p_B + 98304, p_h,
                                             a2s, a2d, p_asB, p_adB, NNODE, 64, 256, 16);
    gat_agg_l2<<<nodeWarpBlocks, TB>>>(b2);

    // ---- Layer 3 ----
    gemm_tc<<<dim3(2, MB), 256, GEMM_SMEM>>>(p_A, p_B + 114688, p_h,
                                             a3s, a3d, p_asA, p_adA, NNODE, 128, 64, 32);
    gat_agg_l3<<<nodeWarpBlocks, TB>>>(b3);

    // ---- Candidate-edge logits (4 edges per warp) ----
    dot_kernel<<<(ECAND / 4 * 32 + TB - 1) / TB, TB>>>(eli, out);
}